// round 1
// baseline (speedup 1.0000x reference)
#include <cuda_runtime.h>

// Problem constants
#define BATCH 16
#define CCH   384          // channels
#define HW    4096         // 64*64 pixels
#define NHEADS 12
#define DHEAD  32
#define QKV_C (3*CCH)      // 1152

// Intermediates as device globals (no cudaMalloc allowed).
// g_qkv: [b][pix][3C]  (channel-contiguous for coalesced attention loads)
// g_o:   [b][pix][C]
__device__ float g_qkv[(size_t)BATCH * HW * QKV_C];
__device__ float g_o[(size_t)BATCH * HW * CCH];

// ---------------------------------------------------------------------------
// Kernel A: qkv_t[b][pix][o] = sum_c x[b][c][pix] * w_qkv[o][c] + b_qkv[o]
// GEMM with M = pixels (4096/batch), N = out-channels (1152), K = 384.
// A operand = x_b, already stored [K][M] (K-major) -> coalesced tile loads.
// B operand = w_qkv [N][K] row-major -> float4 loads along K, scatter to smem.
// ---------------------------------------------------------------------------
__global__ __launch_bounds__(256) void qkv_gemm_kernel(
    const float* __restrict__ x,
    const float* __restrict__ w,
    const float* __restrict__ bias)
{
    __shared__ float As[8][128];  // [k][pix]
    __shared__ float Bs[8][128];  // [k][och]

    const int b  = blockIdx.z;
    const int m0 = blockIdx.x * 128;   // pixel tile (32 tiles)
    const int n0 = blockIdx.y * 128;   // out-channel tile (9 tiles)

    const float* xb  = x + (size_t)b * CCH * HW;
    float*       out = g_qkv + (size_t)b * HW * QKV_C;

    const int tid  = threadIdx.x;
    const int tm0  = (tid >> 4) * 8;
    const int tn0  = (tid & 15) * 8;

    const int a_k  = tid >> 5;          // 0..7
    const int a_m  = (tid & 31) * 4;    // 0..124
    const int b_n  = tid >> 1;          // 0..127
    const int b_k4 = (tid & 1) * 4;     // 0 or 4

    float acc[8][8] = {};

    for (int k0 = 0; k0 < CCH; k0 += 8) {
        float4 av = *reinterpret_cast<const float4*>(
            xb + (size_t)(k0 + a_k) * HW + m0 + a_m);
        *reinterpret_cast<float4*>(&As[a_k][a_m]) = av;

        float4 bv = *reinterpret_cast<const float4*>(
            w + (size_t)(n0 + b_n) * CCH + k0 + b_k4);
        Bs[b_k4 + 0][b_n] = bv.x;
        Bs[b_k4 + 1][b_n] = bv.y;
        Bs[b_k4 + 2][b_n] = bv.z;
        Bs[b_k4 + 3][b_n] = bv.w;
        __syncthreads();

        #pragma unroll
        for (int k = 0; k < 8; k++) {
            float rm[8], rn[8];
            *reinterpret_cast<float4*>(&rm[0]) = *reinterpret_cast<const float4*>(&As[k][tm0]);
            *reinterpret_cast<float4*>(&rm[4]) = *reinterpret_cast<const float4*>(&As[k][tm0 + 4]);
            *reinterpret_cast<float4*>(&rn[0]) = *reinterpret_cast<const float4*>(&Bs[k][tn0]);
            *reinterpret_cast<float4*>(&rn[4]) = *reinterpret_cast<const float4*>(&Bs[k][tn0 + 4]);
            #pragma unroll
            for (int i = 0; i < 8; i++)
                #pragma unroll
                for (int j = 0; j < 8; j++)
                    acc[i][j] += rm[i] * rn[j];
        }
        __syncthreads();
    }

    #pragma unroll
    for (int i = 0; i < 8; i++) {
        size_t row = (size_t)(m0 + tm0 + i) * QKV_C + n0 + tn0;
        #pragma unroll
        for (int j = 0; j < 8; j += 4) {
            float4 v;
            v.x = acc[i][j + 0] + bias[n0 + tn0 + j + 0];
            v.y = acc[i][j + 1] + bias[n0 + tn0 + j + 1];
            v.z = acc[i][j + 2] + bias[n0 + tn0 + j + 2];
            v.w = acc[i][j + 3] + bias[n0 + tn0 + j + 3];
            *reinterpret_cast<float4*>(out + row + j) = v;
        }
    }
}

// ---------------------------------------------------------------------------
// Kernel B: windowed attention. One block per (b, head, window).
// Strided windows (faithful to reference):
//   input  pixel of token (wsh,wsw) in window (hh,ww): h=wsh*8+hh, w=wsw*8+ww
//   output pixel:                                      h'=hh*8+wsh, w'=ww*8+wsw
// ---------------------------------------------------------------------------
__global__ __launch_bounds__(256) void attn_kernel()
{
    __shared__ float qs[64][33];
    __shared__ float ks[64][33];
    __shared__ float vs[64][33];
    __shared__ float s[64][65];

    const int wi   = blockIdx.x;   // 0..63
    const int head = blockIdx.y;   // 0..11
    const int b    = blockIdx.z;   // 0..15
    const int hh   = wi >> 3;
    const int ww   = wi & 7;
    const int tid  = threadIdx.x;

    const float* base = g_qkv + (size_t)b * HW * QKV_C;

    // Load q,k,v: 3*64*32 floats; contiguous 128B per token row (coalesced).
    for (int e = tid; e < 3 * 64 * 32; e += 256) {
        int which = e >> 11;             // 0=q, 1=k, 2=v
        int rem   = e & 2047;
        int tok   = rem >> 5;
        int dd    = rem & 31;
        int wsh = tok >> 3, wsw = tok & 7;
        int pix = (wsh * 8 + hh) * 64 + wsw * 8 + ww;
        float val = base[(size_t)pix * QKV_C + which * CCH + head * DHEAD + dd];
        if (which == 0)      qs[tok][dd] = val;
        else if (which == 1) ks[tok][dd] = val;
        else                 vs[tok][dd] = val;
    }
    __syncthreads();

    // S = Q K^T * scale : each thread does row si, 16 cols strided by 4.
    {
        const int si  = tid >> 2;
        const int sj0 = tid & 3;
        const float scl = 0.17677669529663687f;  // 1/sqrt(32)
        float qr[32];
        #pragma unroll
        for (int dd = 0; dd < 32; dd++) qr[dd] = qs[si][dd];
        for (int jj = 0; jj < 16; jj++) {
            int j = sj0 + jj * 4;
            float acc = 0.f;
            #pragma unroll
            for (int dd = 0; dd < 32; dd++) acc += qr[dd] * ks[j][dd];
            s[si][j] = acc * scl;
        }
    }
    __syncthreads();

    // Row softmax: threads 0..63
    if (tid < 64) {
        float mx = -1e30f;
        #pragma unroll 8
        for (int j = 0; j < 64; j++) mx = fmaxf(mx, s[tid][j]);
        float sum = 0.f;
        #pragma unroll 8
        for (int j = 0; j < 64; j++) {
            float e = __expf(s[tid][j] - mx);
            s[tid][j] = e;
            sum += e;
        }
        float inv = 1.f / sum;
        #pragma unroll 8
        for (int j = 0; j < 64; j++) s[tid][j] *= inv;
    }
    __syncthreads();

    // O = P V : thread handles row r, 8 channels starting at c0.
    {
        const int r  = tid >> 2;
        const int c0 = (tid & 3) * 8;
        float oa[8] = {};
        for (int t = 0; t < 64; t++) {
            float p = s[r][t];
            #pragma unroll
            for (int j = 0; j < 8; j++) oa[j] += p * vs[t][c0 + j];
        }
        int wsh = r >> 3, wsw = r & 7;
        int pixo = (hh * 8 + wsh) * 64 + ww * 8 + wsw;
        float* outp = g_o + ((size_t)b * HW + pixo) * CCH + head * DHEAD + c0;
        float4 v0 = {oa[0], oa[1], oa[2], oa[3]};
        float4 v1 = {oa[4], oa[5], oa[6], oa[7]};
        *reinterpret_cast<float4*>(outp)     = v0;
        *reinterpret_cast<float4*>(outp + 4) = v1;
    }
}

// ---------------------------------------------------------------------------
// Kernel C: out[b][o][pix] = sum_c w_proj[o][c] * g_o[b][pix][c] + b_proj[o]
// GEMM with M = out-channels (384), N = pixels (4096), K = 384.
// ---------------------------------------------------------------------------
__global__ __launch_bounds__(256) void proj_gemm_kernel(
    const float* __restrict__ w,
    const float* __restrict__ bias,
    float* __restrict__ dout)
{
    __shared__ float As[8][128];  // [k][och]
    __shared__ float Bs[8][128];  // [k][pix]

    const int b  = blockIdx.z;
    const int n0 = blockIdx.x * 128;   // pixel tile (32 tiles)
    const int m0 = blockIdx.y * 128;   // out-channel tile (3 tiles)

    const float* ob  = g_o + (size_t)b * HW * CCH;
    float*       out = dout + (size_t)b * CCH * HW;

    const int tid  = threadIdx.x;
    const int tm0  = (tid >> 4) * 8;
    const int tn0  = (tid & 15) * 8;

    const int a_m  = tid >> 1;        // 0..127
    const int a_k4 = (tid & 1) * 4;   // 0 or 4
    const int b_n  = tid >> 1;        // 0..127
    const int b_k4 = (tid & 1) * 4;

    float acc[8][8] = {};

    for (int k0 = 0; k0 < CCH; k0 += 8) {
        float4 av = *reinterpret_cast<const float4*>(
            w + (size_t)(m0 + a_m) * CCH + k0 + a_k4);
        As[a_k4 + 0][a_m] = av.x;
        As[a_k4 + 1][a_m] = av.y;
        As[a_k4 + 2][a_m] = av.z;
        As[a_k4 + 3][a_m] = av.w;

        float4 bv = *reinterpret_cast<const float4*>(
            ob + (size_t)(n0 + b_n) * CCH + k0 + b_k4);
        Bs[b_k4 + 0][b_n] = bv.x;
        Bs[b_k4 + 1][b_n] = bv.y;
        Bs[b_k4 + 2][b_n] = bv.z;
        Bs[b_k4 + 3][b_n] = bv.w;
        __syncthreads();

        #pragma unroll
        for (int k = 0; k < 8; k++) {
            float rm[8], rn[8];
            *reinterpret_cast<float4*>(&rm[0]) = *reinterpret_cast<const float4*>(&As[k][tm0]);
            *reinterpret_cast<float4*>(&rm[4]) = *reinterpret_cast<const float4*>(&As[k][tm0 + 4]);
            *reinterpret_cast<float4*>(&rn[0]) = *reinterpret_cast<const float4*>(&Bs[k][tn0]);
            *reinterpret_cast<float4*>(&rn[4]) = *reinterpret_cast<const float4*>(&Bs[k][tn0 + 4]);
            #pragma unroll
            for (int i = 0; i < 8; i++)
                #pragma unroll
                for (int j = 0; j < 8; j++)
                    acc[i][j] += rm[i] * rn[j];
        }
        __syncthreads();
    }

    #pragma unroll
    for (int i = 0; i < 8; i++) {
        float bi = bias[m0 + tm0 + i];
        size_t row = (size_t)(m0 + tm0 + i) * HW + n0 + tn0;
        #pragma unroll
        for (int j = 0; j < 8; j += 4) {
            float4 v;
            v.x = acc[i][j + 0] + bi;
            v.y = acc[i][j + 1] + bi;
            v.z = acc[i][j + 2] + bi;
            v.w = acc[i][j + 3] + bi;
            *reinterpret_cast<float4*>(out + row + j) = v;
        }
    }
}

// ---------------------------------------------------------------------------
extern "C" void kernel_launch(void* const* d_in, const int* in_sizes, int n_in,
                              void* d_out, int out_size)
{
    const float* x      = (const float*)d_in[0];
    const float* w_qkv  = (const float*)d_in[1];
    const float* b_qkv  = (const float*)d_in[2];
    const float* w_proj = (const float*)d_in[3];
    const float* b_proj = (const float*)d_in[4];
    float* out = (float*)d_out;

    (void)in_sizes; (void)n_in; (void)out_size;

    dim3 gridA(32, 9, BATCH);        // pix tiles, qkv-channel tiles, batch
    qkv_gemm_kernel<<<gridA, 256>>>(x, w_qkv, b_qkv);

    dim3 gridB(64, NHEADS, BATCH);   // windows, heads, batch
    attn_kernel<<<gridB, 256>>>();

    dim3 gridC(32, 3, BATCH);        // pix tiles, channel tiles, batch
    proj_gemm_kernel<<<gridC, 256>>>(w_proj, b_proj, out);
}

// round 3
// speedup vs baseline: 1.9151x; 1.9151x over previous
#include <cuda_runtime.h>
#include <cuda_bf16.h>
#include <cstdint>

// Problem constants
#define BATCH  16
#define CCH    384
#define HW     4096
#define NHEADS 12
#define DHEAD  32
#define QKV_C  1152

#define BK     32
#define NCHUNK (CCH / BK)   // 12

// ---------------------------------------------------------------------------
// Device-global scratch (no cudaMalloc allowed)
// ---------------------------------------------------------------------------
__device__ float g_qkv[(size_t)BATCH * HW * QKV_C];                       // [b][pix][3C]
__device__ __align__(256) __nv_bfloat16 g_xt_hi[(size_t)BATCH * HW * CCH]; // x^T [b][pix][c]
__device__ __align__(256) __nv_bfloat16 g_xt_lo[(size_t)BATCH * HW * CCH];
__device__ __align__(256) __nv_bfloat16 g_o_hi[(size_t)BATCH * HW * CCH];  // attn out
__device__ __align__(256) __nv_bfloat16 g_o_lo[(size_t)BATCH * HW * CCH];
__device__ __align__(256) __nv_bfloat16 g_wq_hi[QKV_C * CCH];
__device__ __align__(256) __nv_bfloat16 g_wq_lo[QKV_C * CCH];
__device__ __align__(256) __nv_bfloat16 g_wp_hi[CCH * CCH];
__device__ __align__(256) __nv_bfloat16 g_wp_lo[CCH * CCH];

// ---------------------------------------------------------------------------
// Helpers
// ---------------------------------------------------------------------------
__device__ __forceinline__ uint32_t smem_u32(const void* p) {
    uint32_t a;
    asm("{ .reg .u64 t; cvta.to.shared.u64 t, %1; cvt.u32.u64 %0, t; }"
        : "=r"(a) : "l"(p));
    return a;
}

__device__ __forceinline__ void split_bf16(float v, __nv_bfloat16& h, __nv_bfloat16& l) {
    h = __float2bfloat16(v);
    l = __float2bfloat16(v - __bfloat162float(h));
}

// smem tile: 128 rows x 32 bf16 (64B/row), 16B chunks swizzled for ldmatrix
__device__ __forceinline__ uint32_t swz(uint32_t row, uint32_t c16) {
    return row * 64u + ((c16 ^ ((row >> 1) & 3u)) * 16u);
}

__device__ __forceinline__ void ldm_x4(uint32_t* r, uint32_t addr) {
    asm volatile("ldmatrix.sync.aligned.m8n8.x4.shared.b16 {%0,%1,%2,%3}, [%4];"
                 : "=r"(r[0]), "=r"(r[1]), "=r"(r[2]), "=r"(r[3]) : "r"(addr));
}

__device__ __forceinline__ void mma16816(float* c, const uint32_t* a, const uint32_t* b) {
    asm volatile(
        "mma.sync.aligned.m16n8k16.row.col.f32.bf16.bf16.f32 "
        "{%0,%1,%2,%3}, {%4,%5,%6,%7}, {%8,%9}, {%0,%1,%2,%3};"
        : "+f"(c[0]), "+f"(c[1]), "+f"(c[2]), "+f"(c[3])
        : "r"(a[0]), "r"(a[1]), "r"(a[2]), "r"(a[3]), "r"(b[0]), "r"(b[1]));
}

#define CP_ASYNC16(dst, src) \
    asm volatile("cp.async.cg.shared.global [%0], [%1], 16;" :: "r"(dst), "l"(src))
#define CP_COMMIT() asm volatile("cp.async.commit_group;")
#define CP_WAIT0()  asm volatile("cp.async.wait_group 0;")

// load one 128x32 bf16 tile (row stride CCH) into swizzled smem via cp.async
__device__ __forceinline__ void load_tile_async(const __nv_bfloat16* __restrict__ src,
                                                int row0, int k0, uint32_t dst, int tid) {
    #pragma unroll
    for (int j = 0; j < 2; j++) {
        int c   = tid + j * 256;
        int row = c >> 2, c16 = c & 3;
        const __nv_bfloat16* g = src + (size_t)(row0 + row) * CCH + k0 + c16 * 8;
        CP_ASYNC16(dst + swz((uint32_t)row, (uint32_t)c16), g);
    }
}

// ---------------------------------------------------------------------------
// Kernel 1: transpose x [b][c][pix] -> bf16 hi/lo [b][pix][c]
// ---------------------------------------------------------------------------
__global__ __launch_bounds__(256) void transpose_split_kernel(const float* __restrict__ x)
{
    __shared__ float t[32][33];
    const int b  = blockIdx.z;
    const int p0 = blockIdx.x * 32;
    const int c0 = blockIdx.y * 32;
    const int tx = threadIdx.x & 31;
    const int ty = threadIdx.x >> 5;

    const float* xb = x + (size_t)b * CCH * HW;
    #pragma unroll
    for (int i = 0; i < 4; i++)
        t[ty + i * 8][tx] = xb[(size_t)(c0 + ty + i * 8) * HW + p0 + tx];
    __syncthreads();

    #pragma unroll
    for (int i = 0; i < 4; i++) {
        int p = p0 + ty + i * 8;
        int c = c0 + tx;
        __nv_bfloat16 h, l;
        split_bf16(t[tx][ty + i * 8], h, l);
        size_t idx = ((size_t)b * HW + p) * CCH + c;
        g_xt_hi[idx] = h;
        g_xt_lo[idx] = l;
    }
}

// ---------------------------------------------------------------------------
// Kernel 2: weight splits (writes fixed device globals; no symbol lookups)
// ---------------------------------------------------------------------------
__global__ void weight_split_kernel(const float* __restrict__ wq,
                                    const float* __restrict__ wp)
{
    int i = blockIdx.x * blockDim.x + threadIdx.x;
    if (i < QKV_C * CCH) {
        __nv_bfloat16 h, l;
        split_bf16(wq[i], h, l);
        g_wq_hi[i] = h; g_wq_lo[i] = l;
    }
    if (i < CCH * CCH) {
        __nv_bfloat16 h, l;
        split_bf16(wp[i], h, l);
        g_wp_hi[i] = h; g_wp_lo[i] = l;
    }
}

// ---------------------------------------------------------------------------
// Tensor-core GEMM (mma.sync bf16, 3-pass hi/lo split, fp32 accumulate)
// D[m=pix(128)][n=och(128)] = A[pix][cch] . B[och][cch]^T
// G==0: A = g_xt, B = w_qkv -> g_qkv [b][pix][1152]
// G==1: A = g_o,  B = w_proj -> out  [b][och][4096]
// ---------------------------------------------------------------------------
#define STAGE_BYTES 32768
#define GEMM_SMEM   65536

template<int G>
__global__ __launch_bounds__(256) void gemm_mma_kernel(const float* __restrict__ bias,
                                                       float* __restrict__ out_base)
{
    extern __shared__ __align__(128) char smem[];
    const uint32_t sbase = smem_u32(smem);
    const int tid = threadIdx.x, wid = tid >> 5, lane = tid & 31;
    const int warp_m = wid & 3;       // 4 warps along m (32 rows each)
    const int warp_n = wid >> 2;      // 2 warps along n (64 cols each)

    const int b  = blockIdx.z;
    const int m0 = blockIdx.x * 128;  // pixel tile
    const int n0 = blockIdx.y * 128;  // out-channel tile

    const __nv_bfloat16* Ahi = (G == 0 ? g_xt_hi : g_o_hi) + (size_t)b * HW * CCH;
    const __nv_bfloat16* Alo = (G == 0 ? g_xt_lo : g_o_lo) + (size_t)b * HW * CCH;
    const __nv_bfloat16* Bhi = (G == 0 ? g_wq_hi : g_wp_hi);
    const __nv_bfloat16* Blo = (G == 0 ? g_wq_lo : g_wp_lo);

    float acc[2][8][4] = {};

    // prologue: chunk 0 -> stage 0
    load_tile_async(Ahi, m0, 0, sbase + 0,     tid);
    load_tile_async(Alo, m0, 0, sbase + 8192,  tid);
    load_tile_async(Bhi, n0, 0, sbase + 16384, tid);
    load_tile_async(Blo, n0, 0, sbase + 24576, tid);
    CP_COMMIT();
    CP_WAIT0();
    __syncthreads();

    const int lrow = lane & 7;          // row within 8x8 block
    const int lblk = lane >> 3;         // block id 0..3

    #pragma unroll 1
    for (int i = 0; i < NCHUNK; i++) {
        const int cur = i & 1;
        if (i + 1 < NCHUNK) {
            const uint32_t nb = sbase + (cur ^ 1) * STAGE_BYTES;
            const int k0 = (i + 1) * BK;
            load_tile_async(Ahi, m0, k0, nb + 0,     tid);
            load_tile_async(Alo, m0, k0, nb + 8192,  tid);
            load_tile_async(Bhi, n0, k0, nb + 16384, tid);
            load_tile_async(Blo, n0, k0, nb + 24576, tid);
            CP_COMMIT();
        }

        const uint32_t sAh = sbase + cur * STAGE_BYTES;
        const uint32_t sAl = sAh + 8192;
        const uint32_t sBh = sAh + 16384;
        const uint32_t sBl = sAh + 24576;

        #pragma unroll
        for (int ks = 0; ks < 2; ks++) {
            // A fragments: block order [m0-7,k0-7],[m8-15,k0-7],[m0-7,k8-15],[m8-15,k8-15]
            uint32_t Ah[2][4], Al[2][4];
            #pragma unroll
            for (int mt = 0; mt < 2; mt++) {
                uint32_t row = (uint32_t)(warp_m * 32 + mt * 16 + (lblk & 1) * 8 + lrow);
                uint32_t c16 = (uint32_t)(ks * 2 + (lblk >> 1));
                uint32_t off = swz(row, c16);
                ldm_x4(Ah[mt], sAh + off);
                ldm_x4(Al[mt], sAl + off);
            }
            // B fragments: block order [n0-7,k0-7],[n0-7,k8-15],[n8-15,k0-7],[n8-15,k8-15]
            uint32_t Bh[8][2], Bl[8][2];
            #pragma unroll
            for (int np = 0; np < 4; np++) {
                uint32_t row = (uint32_t)(warp_n * 64 + np * 16 + (lblk >> 1) * 8 + lrow);
                uint32_t c16 = (uint32_t)(ks * 2 + (lblk & 1));
                uint32_t off = swz(row, c16);
                uint32_t r[4];
                ldm_x4(r, sBh + off);
                Bh[np*2][0] = r[0]; Bh[np*2][1] = r[1];
                Bh[np*2+1][0] = r[2]; Bh[np*2+1][1] = r[3];
            }
            // pass 1: hi*hi ; pass 2: lo*hi (Bh still live)
            #pragma unroll
            for (int mt = 0; mt < 2; mt++)
                #pragma unroll
                for (int nt = 0; nt < 8; nt++)
                    mma16816(acc[mt][nt], Ah[mt], Bh[nt]);
            #pragma unroll
            for (int mt = 0; mt < 2; mt++)
                #pragma unroll
                for (int nt = 0; nt < 8; nt++)
                    mma16816(acc[mt][nt], Al[mt], Bh[nt]);
            // pass 3: hi*lo
            #pragma unroll
            for (int np = 0; np < 4; np++) {
                uint32_t row = (uint32_t)(warp_n * 64 + np * 16 + (lblk >> 1) * 8 + lrow);
                uint32_t c16 = (uint32_t)(ks * 2 + (lblk & 1));
                uint32_t r[4];
                ldm_x4(r, sBl + swz(row, c16));
                Bl[np*2][0] = r[0]; Bl[np*2][1] = r[1];
                Bl[np*2+1][0] = r[2]; Bl[np*2+1][1] = r[3];
            }
            #pragma unroll
            for (int mt = 0; mt < 2; mt++)
                #pragma unroll
                for (int nt = 0; nt < 8; nt++)
                    mma16816(acc[mt][nt], Ah[mt], Bl[nt]);
        }

        if (i + 1 < NCHUNK) CP_WAIT0();
        __syncthreads();
    }

    // ------------------- epilogue (smem-staged, coalesced) -------------------
    if (G == 0) {
        constexpr int PAD = 68;                      // floats; 68*4 % 16 == 0
        float* st = reinterpret_cast<float*>(smem);  // [128][68]
        float* outb = g_qkv + (size_t)b * HW * QKV_C;
        #pragma unroll 1
        for (int h = 0; h < 2; h++) {
            __syncthreads();
            if (warp_n == h) {
                #pragma unroll
                for (int mt = 0; mt < 2; mt++)
                    #pragma unroll
                    for (int nt = 0; nt < 8; nt++) {
                        int ml = warp_m * 32 + mt * 16 + (lane >> 2);
                        int nl = nt * 8 + (lane & 3) * 2;
                        st[ml * PAD + nl]           = acc[mt][nt][0];
                        st[ml * PAD + nl + 1]       = acc[mt][nt][1];
                        st[(ml + 8) * PAD + nl]     = acc[mt][nt][2];
                        st[(ml + 8) * PAD + nl + 1] = acc[mt][nt][3];
                    }
            }
            __syncthreads();
            #pragma unroll
            for (int j = 0; j < 8; j++) {
                int fi  = tid + j * 256;
                int row = fi >> 4;
                int c4  = (fi & 15) * 4;
                int n   = n0 + h * 64 + c4;
                float4 v  = *reinterpret_cast<float4*>(&st[row * PAD + c4]);
                float4 bb = *reinterpret_cast<const float4*>(&bias[n]);
                v.x += bb.x; v.y += bb.y; v.z += bb.z; v.w += bb.w;
                *reinterpret_cast<float4*>(&outb[(size_t)(m0 + row) * QKV_C + n]) = v;
            }
        }
    } else {
        constexpr int PAD = 132;                     // floats; 132*4 % 16 == 0
        float* st = reinterpret_cast<float*>(smem);  // [64][132]
        float* outb = out_base + (size_t)b * CCH * HW;
        #pragma unroll 1
        for (int h = 0; h < 2; h++) {
            __syncthreads();
            if (warp_n == h) {
                #pragma unroll
                for (int mt = 0; mt < 2; mt++)
                    #pragma unroll
                    for (int nt = 0; nt < 8; nt++) {
                        int ml = warp_m * 32 + mt * 16 + (lane >> 2);
                        int nl = nt * 8 + (lane & 3) * 2;
                        st[nl * PAD + ml]           = acc[mt][nt][0];
                        st[(nl + 1) * PAD + ml]     = acc[mt][nt][1];
                        st[nl * PAD + ml + 8]       = acc[mt][nt][2];
                        st[(nl + 1) * PAD + ml + 8] = acc[mt][nt][3];
                    }
            }
            __syncthreads();
            #pragma unroll
            for (int j = 0; j < 8; j++) {
                int fi  = tid + j * 256;
                int row = fi >> 5;                   // och local 0..63
                int c4  = (fi & 31) * 4;             // pix local
                int och = n0 + h * 64 + row;
                float4 v = *reinterpret_cast<float4*>(&st[row * PAD + c4]);
                float bi = bias[och];
                v.x += bi; v.y += bi; v.z += bi; v.w += bi;
                *reinterpret_cast<float4*>(&outb[(size_t)och * HW + m0 + c4]) = v;
            }
        }
    }
}

// ---------------------------------------------------------------------------
// Attention: one block per (b, head, window); fp32 math; bf16-split output.
// Strided windows (faithful to reference).
// ---------------------------------------------------------------------------
__global__ __launch_bounds__(256) void attn_kernel()
{
    __shared__ float qs[64][33];
    __shared__ float ks[64][33];
    __shared__ float vs[64][33];
    __shared__ float s[64][65];

    const int wi   = blockIdx.x;
    const int head = blockIdx.y;
    const int b    = blockIdx.z;
    const int hh   = wi >> 3;
    const int ww   = wi & 7;
    const int tid  = threadIdx.x;

    const float* base = g_qkv + (size_t)b * HW * QKV_C;

    for (int e = tid; e < 3 * 64 * 32; e += 256) {
        int which = e >> 11;
        int rem   = e & 2047;
        int tok   = rem >> 5;
        int dd    = rem & 31;
        int wsh = tok >> 3, wsw = tok & 7;
        int pix = (wsh * 8 + hh) * 64 + wsw * 8 + ww;
        float val = base[(size_t)pix * QKV_C + which * CCH + head * DHEAD + dd];
        if (which == 0)      qs[tok][dd] = val;
        else if (which == 1) ks[tok][dd] = val;
        else                 vs[tok][dd] = val;
    }
    __syncthreads();

    {
        const int si  = tid >> 2;
        const int sj0 = tid & 3;
        const float scl = 0.17677669529663687f;
        float qr[32];
        #pragma unroll
        for (int dd = 0; dd < 32; dd++) qr[dd] = qs[si][dd];
        for (int jj = 0; jj < 16; jj++) {
            int j = sj0 + jj * 4;
            float a = 0.f;
            #pragma unroll
            for (int dd = 0; dd < 32; dd++) a += qr[dd] * ks[j][dd];
            s[si][j] = a * scl;
        }
    }
    __syncthreads();

    if (tid < 64) {
        float mx = -1e30f;
        #pragma unroll 8
        for (int j = 0; j < 64; j++) mx = fmaxf(mx, s[tid][j]);
        float sum = 0.f;
        #pragma unroll 8
        for (int j = 0; j < 64; j++) {
            float e = __expf(s[tid][j] - mx);
            s[tid][j] = e;
            sum += e;
        }
        float inv = 1.f / sum;
        #pragma unroll 8
        for (int j = 0; j < 64; j++) s[tid][j] *= inv;
    }
    __syncthreads();

    {
        const int r  = tid >> 2;
        const int c0 = (tid & 3) * 8;
        float oa[8] = {};
        for (int t = 0; t < 64; t++) {
            float p = s[r][t];
            #pragma unroll
            for (int j = 0; j < 8; j++) oa[j] += p * vs[t][c0 + j];
        }
        int wsh = r >> 3, wsw = r & 7;
        int pixo = (hh * 8 + wsh) * 64 + ww * 8 + wsw;
        size_t off = ((size_t)b * HW + pixo) * CCH + head * DHEAD + c0;

        alignas(16) __nv_bfloat16 h8[8], l8[8];
        #pragma unroll
        for (int j = 0; j < 8; j++) split_bf16(oa[j], h8[j], l8[j]);
        *reinterpret_cast<uint4*>(g_o_hi + off) = *reinterpret_cast<uint4*>(h8);
        *reinterpret_cast<uint4*>(g_o_lo + off) = *reinterpret_cast<uint4*>(l8);
    }
}

// ---------------------------------------------------------------------------
extern "C" void kernel_launch(void* const* d_in, const int* in_sizes, int n_in,
                              void* d_out, int out_size)
{
    const float* x      = (const float*)d_in[0];
    const float* w_qkv  = (const float*)d_in[1];
    const float* b_qkv  = (const float*)d_in[2];
    const float* w_proj = (const float*)d_in[3];
    const float* b_proj = (const float*)d_in[4];
    float* out = (float*)d_out;
    (void)in_sizes; (void)n_in; (void)out_size;

    cudaFuncSetAttribute(gemm_mma_kernel<0>,
                         cudaFuncAttributeMaxDynamicSharedMemorySize, GEMM_SMEM);
    cudaFuncSetAttribute(gemm_mma_kernel<1>,
                         cudaFuncAttributeMaxDynamicSharedMemorySize, GEMM_SMEM);

    weight_split_kernel<<<(QKV_C * CCH + 255) / 256, 256>>>(w_qkv, w_proj);

    dim3 gT(HW / 32, CCH / 32, BATCH);
    transpose_split_kernel<<<gT, 256>>>(x);

    dim3 g1(HW / 128, QKV_C / 128, BATCH);   // 32 x 9 x 16
    gemm_mma_kernel<0><<<g1, 256, GEMM_SMEM>>>(b_qkv, nullptr);

    dim3 gA(64, NHEADS, BATCH);
    attn_kernel<<<gA, 256>>>();

    dim3 g2(HW / 128, CCH / 128, BATCH);     // 32 x 3 x 16
    gemm_mma_kernel<1><<<g2, 256, GEMM_SMEM>>>(b_proj, out);
}

// round 4
// speedup vs baseline: 2.5974x; 1.3562x over previous
#include <cuda_runtime.h>
#include <cuda_bf16.h>
#include <cstdint>

// Problem constants
#define BATCH  16
#define CCH    384
#define HW     4096
#define NHEADS 12
#define DHEAD  32
#define QKV_C  1152

#define BK     32
#define NCHUNK (CCH / BK)   // 12

// ---------------------------------------------------------------------------
// Device-global scratch (no cudaMalloc allowed)
// ---------------------------------------------------------------------------
__device__ float g_qkv[(size_t)BATCH * HW * QKV_C];                       // [b][pix][3C]
__device__ __align__(256) __nv_bfloat16 g_xt_hi[(size_t)BATCH * HW * CCH]; // x^T [b][pix][c]
__device__ __align__(256) __nv_bfloat16 g_xt_lo[(size_t)BATCH * HW * CCH];
__device__ __align__(256) __nv_bfloat16 g_o_hi[(size_t)BATCH * HW * CCH];  // attn out
__device__ __align__(256) __nv_bfloat16 g_o_lo[(size_t)BATCH * HW * CCH];
__device__ __align__(256) __nv_bfloat16 g_wq_hi[QKV_C * CCH];
__device__ __align__(256) __nv_bfloat16 g_wq_lo[QKV_C * CCH];
__device__ __align__(256) __nv_bfloat16 g_wp_hi[CCH * CCH];
__device__ __align__(256) __nv_bfloat16 g_wp_lo[CCH * CCH];

// ---------------------------------------------------------------------------
// Helpers
// ---------------------------------------------------------------------------
__device__ __forceinline__ uint32_t smem_u32(const void* p) {
    uint32_t a;
    asm("{ .reg .u64 t; cvta.to.shared.u64 t, %1; cvt.u32.u64 %0, t; }"
        : "=r"(a) : "l"(p));
    return a;
}

__device__ __forceinline__ void split_bf16(float v, __nv_bfloat16& h, __nv_bfloat16& l) {
    h = __float2bfloat16(v);
    l = __float2bfloat16(v - __bfloat162float(h));
}

// hi/lo split of 2 floats packed into 2 u32 (low half = first value)
__device__ __forceinline__ void split2_pack(float a, float b, uint32_t& hi, uint32_t& lo) {
    __nv_bfloat16 ha = __float2bfloat16(a), hb = __float2bfloat16(b);
    float ra = a - __bfloat162float(ha), rb = b - __bfloat162float(hb);
    __nv_bfloat16 la = __float2bfloat16(ra), lb = __float2bfloat16(rb);
    uint16_t uha = *reinterpret_cast<uint16_t*>(&ha);
    uint16_t uhb = *reinterpret_cast<uint16_t*>(&hb);
    uint16_t ula = *reinterpret_cast<uint16_t*>(&la);
    uint16_t ulb = *reinterpret_cast<uint16_t*>(&lb);
    hi = (uint32_t)uha | ((uint32_t)uhb << 16);
    lo = (uint32_t)ula | ((uint32_t)ulb << 16);
}

// smem tile: rows of 32 bf16 (64B/row), 16B chunks swizzled for ldmatrix
__device__ __forceinline__ uint32_t swz(uint32_t row, uint32_t c16) {
    return row * 64u + ((c16 ^ ((row >> 1) & 3u)) * 16u);
}

__device__ __forceinline__ void ldm_x4(uint32_t* r, uint32_t addr) {
    asm volatile("ldmatrix.sync.aligned.m8n8.x4.shared.b16 {%0,%1,%2,%3}, [%4];"
                 : "=r"(r[0]), "=r"(r[1]), "=r"(r[2]), "=r"(r[3]) : "r"(addr));
}

__device__ __forceinline__ void ldm_x4_trans(uint32_t* r, uint32_t addr) {
    asm volatile("ldmatrix.sync.aligned.m8n8.x4.trans.shared.b16 {%0,%1,%2,%3}, [%4];"
                 : "=r"(r[0]), "=r"(r[1]), "=r"(r[2]), "=r"(r[3]) : "r"(addr));
}

__device__ __forceinline__ void mma16816(float* c, const uint32_t* a, const uint32_t* b) {
    asm volatile(
        "mma.sync.aligned.m16n8k16.row.col.f32.bf16.bf16.f32 "
        "{%0,%1,%2,%3}, {%4,%5,%6,%7}, {%8,%9}, {%0,%1,%2,%3};"
        : "+f"(c[0]), "+f"(c[1]), "+f"(c[2]), "+f"(c[3])
        : "r"(a[0]), "r"(a[1]), "r"(a[2]), "r"(a[3]), "r"(b[0]), "r"(b[1]));
}

#define CP_ASYNC16(dst, src) \
    asm volatile("cp.async.cg.shared.global [%0], [%1], 16;" :: "r"(dst), "l"(src))
#define CP_COMMIT() asm volatile("cp.async.commit_group;")
#define CP_WAIT0()  asm volatile("cp.async.wait_group 0;")

// load one 128x32 bf16 tile (row stride CCH) into swizzled smem via cp.async
__device__ __forceinline__ void load_tile_async(const __nv_bfloat16* __restrict__ src,
                                                int row0, int k0, uint32_t dst, int tid) {
    #pragma unroll
    for (int j = 0; j < 2; j++) {
        int c   = tid + j * 256;
        int row = c >> 2, c16 = c & 3;
        const __nv_bfloat16* g = src + (size_t)(row0 + row) * CCH + k0 + c16 * 8;
        CP_ASYNC16(dst + swz((uint32_t)row, (uint32_t)c16), g);
    }
}

// ---------------------------------------------------------------------------
// Kernel 1: transpose x [b][c][pix] -> bf16 hi/lo [b][pix][c]
// ---------------------------------------------------------------------------
__global__ __launch_bounds__(256) void transpose_split_kernel(const float* __restrict__ x)
{
    __shared__ float t[32][33];
    const int b  = blockIdx.z;
    const int p0 = blockIdx.x * 32;
    const int c0 = blockIdx.y * 32;
    const int tx = threadIdx.x & 31;
    const int ty = threadIdx.x >> 5;

    const float* xb = x + (size_t)b * CCH * HW;
    #pragma unroll
    for (int i = 0; i < 4; i++)
        t[ty + i * 8][tx] = xb[(size_t)(c0 + ty + i * 8) * HW + p0 + tx];
    __syncthreads();

    #pragma unroll
    for (int i = 0; i < 4; i++) {
        int p = p0 + ty + i * 8;
        int c = c0 + tx;
        __nv_bfloat16 h, l;
        split_bf16(t[tx][ty + i * 8], h, l);
        size_t idx = ((size_t)b * HW + p) * CCH + c;
        g_xt_hi[idx] = h;
        g_xt_lo[idx] = l;
    }
}

// ---------------------------------------------------------------------------
// Kernel 2: weight splits
// ---------------------------------------------------------------------------
__global__ void weight_split_kernel(const float* __restrict__ wq,
                                    const float* __restrict__ wp)
{
    int i = blockIdx.x * blockDim.x + threadIdx.x;
    if (i < QKV_C * CCH) {
        __nv_bfloat16 h, l;
        split_bf16(wq[i], h, l);
        g_wq_hi[i] = h; g_wq_lo[i] = l;
    }
    if (i < CCH * CCH) {
        __nv_bfloat16 h, l;
        split_bf16(wp[i], h, l);
        g_wp_hi[i] = h; g_wp_lo[i] = l;
    }
}

// ---------------------------------------------------------------------------
// Tensor-core GEMM (mma.sync bf16, 3-pass hi/lo split, fp32 accumulate)
// G==0: A = g_xt, B = w_qkv -> g_qkv [b][pix][1152]
// G==1: A = g_o,  B = w_proj -> out  [b][och][4096]
// ---------------------------------------------------------------------------
#define STAGE_BYTES 32768
#define GEMM_SMEM   65536

template<int G>
__global__ __launch_bounds__(256) void gemm_mma_kernel(const float* __restrict__ bias,
                                                       float* __restrict__ out_base)
{
    extern __shared__ __align__(128) char smem[];
    const uint32_t sbase = smem_u32(smem);
    const int tid = threadIdx.x, wid = tid >> 5, lane = tid & 31;
    const int warp_m = wid & 3;
    const int warp_n = wid >> 2;

    const int b  = blockIdx.z;
    const int m0 = blockIdx.x * 128;
    const int n0 = blockIdx.y * 128;

    const __nv_bfloat16* Ahi = (G == 0 ? g_xt_hi : g_o_hi) + (size_t)b * HW * CCH;
    const __nv_bfloat16* Alo = (G == 0 ? g_xt_lo : g_o_lo) + (size_t)b * HW * CCH;
    const __nv_bfloat16* Bhi = (G == 0 ? g_wq_hi : g_wp_hi);
    const __nv_bfloat16* Blo = (G == 0 ? g_wq_lo : g_wp_lo);

    float acc[2][8][4] = {};

    load_tile_async(Ahi, m0, 0, sbase + 0,     tid);
    load_tile_async(Alo, m0, 0, sbase + 8192,  tid);
    load_tile_async(Bhi, n0, 0, sbase + 16384, tid);
    load_tile_async(Blo, n0, 0, sbase + 24576, tid);
    CP_COMMIT();
    CP_WAIT0();
    __syncthreads();

    const int lrow = lane & 7;
    const int lblk = lane >> 3;

    #pragma unroll 1
    for (int i = 0; i < NCHUNK; i++) {
        const int cur = i & 1;
        if (i + 1 < NCHUNK) {
            const uint32_t nb = sbase + (cur ^ 1) * STAGE_BYTES;
            const int k0 = (i + 1) * BK;
            load_tile_async(Ahi, m0, k0, nb + 0,     tid);
            load_tile_async(Alo, m0, k0, nb + 8192,  tid);
            load_tile_async(Bhi, n0, k0, nb + 16384, tid);
            load_tile_async(Blo, n0, k0, nb + 24576, tid);
            CP_COMMIT();
        }

        const uint32_t sAh = sbase + cur * STAGE_BYTES;
        const uint32_t sAl = sAh + 8192;
        const uint32_t sBh = sAh + 16384;
        const uint32_t sBl = sAh + 24576;

        #pragma unroll
        for (int ks = 0; ks < 2; ks++) {
            uint32_t Ah[2][4], Al[2][4];
            #pragma unroll
            for (int mt = 0; mt < 2; mt++) {
                uint32_t row = (uint32_t)(warp_m * 32 + mt * 16 + (lblk & 1) * 8 + lrow);
                uint32_t c16 = (uint32_t)(ks * 2 + (lblk >> 1));
                uint32_t off = swz(row, c16);
                ldm_x4(Ah[mt], sAh + off);
                ldm_x4(Al[mt], sAl + off);
            }
            uint32_t Bh[8][2], Bl[8][2];
            #pragma unroll
            for (int np = 0; np < 4; np++) {
                uint32_t row = (uint32_t)(warp_n * 64 + np * 16 + (lblk >> 1) * 8 + lrow);
                uint32_t c16 = (uint32_t)(ks * 2 + (lblk & 1));
                uint32_t r[4];
                ldm_x4(r, sBh + swz(row, c16));
                Bh[np*2][0] = r[0]; Bh[np*2][1] = r[1];
                Bh[np*2+1][0] = r[2]; Bh[np*2+1][1] = r[3];
            }
            #pragma unroll
            for (int mt = 0; mt < 2; mt++)
                #pragma unroll
                for (int nt = 0; nt < 8; nt++)
                    mma16816(acc[mt][nt], Ah[mt], Bh[nt]);
            #pragma unroll
            for (int mt = 0; mt < 2; mt++)
                #pragma unroll
                for (int nt = 0; nt < 8; nt++)
                    mma16816(acc[mt][nt], Al[mt], Bh[nt]);
            #pragma unroll
            for (int np = 0; np < 4; np++) {
                uint32_t row = (uint32_t)(warp_n * 64 + np * 16 + (lblk >> 1) * 8 + lrow);
                uint32_t c16 = (uint32_t)(ks * 2 + (lblk & 1));
                uint32_t r[4];
                ldm_x4(r, sBl + swz(row, c16));
                Bl[np*2][0] = r[0]; Bl[np*2][1] = r[1];
                Bl[np*2+1][0] = r[2]; Bl[np*2+1][1] = r[3];
            }
            #pragma unroll
            for (int mt = 0; mt < 2; mt++)
                #pragma unroll
                for (int nt = 0; nt < 8; nt++)
                    mma16816(acc[mt][nt], Ah[mt], Bl[nt]);
        }

        if (i + 1 < NCHUNK) CP_WAIT0();
        __syncthreads();
    }

    if (G == 0) {
        constexpr int PAD = 68;
        float* st = reinterpret_cast<float*>(smem);
        float* outb = g_qkv + (size_t)b * HW * QKV_C;
        #pragma unroll 1
        for (int h = 0; h < 2; h++) {
            __syncthreads();
            if (warp_n == h) {
                #pragma unroll
                for (int mt = 0; mt < 2; mt++)
                    #pragma unroll
                    for (int nt = 0; nt < 8; nt++) {
                        int ml = warp_m * 32 + mt * 16 + (lane >> 2);
                        int nl = nt * 8 + (lane & 3) * 2;
                        st[ml * PAD + nl]           = acc[mt][nt][0];
                        st[ml * PAD + nl + 1]       = acc[mt][nt][1];
                        st[(ml + 8) * PAD + nl]     = acc[mt][nt][2];
                        st[(ml + 8) * PAD + nl + 1] = acc[mt][nt][3];
                    }
            }
            __syncthreads();
            #pragma unroll
            for (int j = 0; j < 8; j++) {
                int fi  = tid + j * 256;
                int row = fi >> 4;
                int c4  = (fi & 15) * 4;
                int n   = n0 + h * 64 + c4;
                float4 v  = *reinterpret_cast<float4*>(&st[row * PAD + c4]);
                float4 bb = *reinterpret_cast<const float4*>(&bias[n]);
                v.x += bb.x; v.y += bb.y; v.z += bb.z; v.w += bb.w;
                *reinterpret_cast<float4*>(&outb[(size_t)(m0 + row) * QKV_C + n]) = v;
            }
        }
    } else {
        constexpr int PAD = 132;
        float* st = reinterpret_cast<float*>(smem);
        float* outb = out_base + (size_t)b * CCH * HW;
        #pragma unroll 1
        for (int h = 0; h < 2; h++) {
            __syncthreads();
            if (warp_n == h) {
                #pragma unroll
                for (int mt = 0; mt < 2; mt++)
                    #pragma unroll
                    for (int nt = 0; nt < 8; nt++) {
                        int ml = warp_m * 32 + mt * 16 + (lane >> 2);
                        int nl = nt * 8 + (lane & 3) * 2;
                        st[nl * PAD + ml]           = acc[mt][nt][0];
                        st[(nl + 1) * PAD + ml]     = acc[mt][nt][1];
                        st[nl * PAD + ml + 8]       = acc[mt][nt][2];
                        st[(nl + 1) * PAD + ml + 8] = acc[mt][nt][3];
                    }
            }
            __syncthreads();
            #pragma unroll
            for (int j = 0; j < 8; j++) {
                int fi  = tid + j * 256;
                int row = fi >> 5;
                int c4  = (fi & 31) * 4;
                int och = n0 + h * 64 + row;
                float4 v = *reinterpret_cast<float4*>(&st[row * PAD + c4]);
                float bi = bias[och];
                v.x += bi; v.y += bi; v.z += bi; v.w += bi;
                *reinterpret_cast<float4*>(&outb[(size_t)och * HW + m0 + c4]) = v;
            }
        }
    }
}

// ---------------------------------------------------------------------------
// Attention via mma.sync (3-pass bf16 split), 1 block = (b, head, window).
// 4 warps; warp w owns query rows 16w..16w+15 (m16). Strided windows.
// ---------------------------------------------------------------------------
__global__ __launch_bounds__(128) void attn_mma_kernel()
{
    __shared__ __align__(128) __nv_bfloat16 sq_hi[64 * 32];
    __shared__ __align__(128) __nv_bfloat16 sq_lo[64 * 32];
    __shared__ __align__(128) __nv_bfloat16 sk_hi[64 * 32];
    __shared__ __align__(128) __nv_bfloat16 sk_lo[64 * 32];
    __shared__ __align__(128) __nv_bfloat16 sv_hi[64 * 32];
    __shared__ __align__(128) __nv_bfloat16 sv_lo[64 * 32];

    const int wi   = blockIdx.x;
    const int head = blockIdx.y;
    const int b    = blockIdx.z;
    const int hh   = wi >> 3;
    const int ww   = wi & 7;
    const int tid  = threadIdx.x;
    const int wid  = tid >> 5;
    const int lane = tid & 31;

    const uint32_t aq_hi = smem_u32(sq_hi), aq_lo = smem_u32(sq_lo);
    const uint32_t ak_hi = smem_u32(sk_hi), ak_lo = smem_u32(sk_lo);
    const uint32_t av_hi = smem_u32(sv_hi), av_lo = smem_u32(sv_lo);

    const float* base = g_qkv + (size_t)b * HW * QKV_C + (size_t)head * DHEAD;
    const float SCALE = 0.17677669529663687f;

    // ---- load q,k,v; split to bf16 hi/lo in swizzled smem -------------------
    // 1536 float4 total (3 tensors x 64 tok x 8 float4); 12 iters x 128 thr
    #pragma unroll 1
    for (int it = 0; it < 12; it++) {
        int f4  = tid + it * 128;
        int ten = f4 >> 9;             // 0=q 1=k 2=v
        int rem = f4 & 511;
        int tok = rem >> 3;
        int c4  = rem & 7;
        int wsh = tok >> 3, wsw = tok & 7;
        int pix = (wsh * 8 + hh) * 64 + wsw * 8 + ww;
        float4 v = *reinterpret_cast<const float4*>(
            base + (size_t)pix * QKV_C + ten * CCH + c4 * 4);
        float s = (ten == 0) ? SCALE : 1.0f;
        uint32_t h01, l01, h23, l23;
        split2_pack(v.x * s, v.y * s, h01, l01);
        split2_pack(v.z * s, v.w * s, h23, l23);
        uint32_t hbase = (ten == 0) ? aq_hi : (ten == 1) ? ak_hi : av_hi;
        uint32_t lbase = (ten == 0) ? aq_lo : (ten == 1) ? ak_lo : av_lo;
        uint32_t off = swz((uint32_t)tok, (uint32_t)(c4 >> 1)) + (uint32_t)(c4 & 1) * 8;
        uint2 hv = { h01, h23 }, lv = { l01, l23 };
        asm volatile("st.shared.v2.b32 [%0], {%1,%2};" :: "r"(hbase + off), "r"(hv.x), "r"(hv.y));
        asm volatile("st.shared.v2.b32 [%0], {%1,%2};" :: "r"(lbase + off), "r"(lv.x), "r"(lv.y));
    }
    __syncthreads();

    const int lrow = lane & 7;
    const int lblk = lane >> 3;

    // ---- S = Q K^T (scaled), 3-pass split -----------------------------------
    float acc[8][4] = {};
    #pragma unroll
    for (int ks = 0; ks < 2; ks++) {
        uint32_t Ah[4], Al[4];
        {
            uint32_t row = (uint32_t)(wid * 16 + (lblk & 1) * 8 + lrow);
            uint32_t c16 = (uint32_t)(ks * 2 + (lblk >> 1));
            uint32_t off = swz(row, c16);
            ldm_x4(Ah, aq_hi + off);
            ldm_x4(Al, aq_lo + off);
        }
        uint32_t Bh[8][2], Bl[8][2];
        #pragma unroll
        for (int np = 0; np < 4; np++) {
            uint32_t row = (uint32_t)(np * 16 + (lblk >> 1) * 8 + lrow);
            uint32_t c16 = (uint32_t)(ks * 2 + (lblk & 1));
            uint32_t r[4];
            ldm_x4(r, ak_hi + swz(row, c16));
            Bh[np*2][0] = r[0]; Bh[np*2][1] = r[1];
            Bh[np*2+1][0] = r[2]; Bh[np*2+1][1] = r[3];
            ldm_x4(r, ak_lo + swz(row, c16));
            Bl[np*2][0] = r[0]; Bl[np*2][1] = r[1];
            Bl[np*2+1][0] = r[2]; Bl[np*2+1][1] = r[3];
        }
        #pragma unroll
        for (int nt = 0; nt < 8; nt++) mma16816(acc[nt], Ah, Bh[nt]);
        #pragma unroll
        for (int nt = 0; nt < 8; nt++) mma16816(acc[nt], Al, Bh[nt]);
        #pragma unroll
        for (int nt = 0; nt < 8; nt++) mma16816(acc[nt], Ah, Bl[nt]);
    }

    // ---- softmax in registers ----------------------------------------------
    // thread owns rows r = 16*wid + lane/4 and r+8; cols nt*8 + (lane%4)*2 +{0,1}
    float mx0 = -1e30f, mx1 = -1e30f;
    #pragma unroll
    for (int nt = 0; nt < 8; nt++) {
        mx0 = fmaxf(mx0, fmaxf(acc[nt][0], acc[nt][1]));
        mx1 = fmaxf(mx1, fmaxf(acc[nt][2], acc[nt][3]));
    }
    #pragma unroll
    for (int d = 1; d <= 2; d <<= 1) {
        mx0 = fmaxf(mx0, __shfl_xor_sync(0xffffffffu, mx0, d));
        mx1 = fmaxf(mx1, __shfl_xor_sync(0xffffffffu, mx1, d));
    }
    float s0 = 0.f, s1 = 0.f;
    #pragma unroll
    for (int nt = 0; nt < 8; nt++) {
        acc[nt][0] = __expf(acc[nt][0] - mx0);
        acc[nt][1] = __expf(acc[nt][1] - mx0);
        acc[nt][2] = __expf(acc[nt][2] - mx1);
        acc[nt][3] = __expf(acc[nt][3] - mx1);
        s0 += acc[nt][0] + acc[nt][1];
        s1 += acc[nt][2] + acc[nt][3];
    }
    #pragma unroll
    for (int d = 1; d <= 2; d <<= 1) {
        s0 += __shfl_xor_sync(0xffffffffu, s0, d);
        s1 += __shfl_xor_sync(0xffffffffu, s1, d);
    }
    const float inv0 = 1.f / s0, inv1 = 1.f / s1;

    // ---- O = P V, P packed straight from accumulators (3-pass) --------------
    float o[4][4] = {};
    #pragma unroll
    for (int j = 0; j < 4; j++) {          // k-step: kv tokens 16j..16j+15
        uint32_t aPh[4], aPl[4];
        split2_pack(acc[2*j][0],   acc[2*j][1],   aPh[0], aPl[0]);
        split2_pack(acc[2*j][2],   acc[2*j][3],   aPh[1], aPl[1]);
        split2_pack(acc[2*j+1][0], acc[2*j+1][1], aPh[2], aPl[2]);
        split2_pack(acc[2*j+1][2], acc[2*j+1][3], aPh[3], aPl[3]);

        uint32_t Bvh[4][2], Bvl[4][2];
        #pragma unroll
        for (int a = 0; a < 2; a++) {
            uint32_t row = (uint32_t)(16 * j + lrow + (lblk & 1) * 8);
            uint32_t c16 = (uint32_t)(2 * a + (lblk >> 1));
            uint32_t r[4];
            ldm_x4_trans(r, av_hi + swz(row, c16));
            Bvh[2*a][0] = r[0]; Bvh[2*a][1] = r[1];
            Bvh[2*a+1][0] = r[2]; Bvh[2*a+1][1] = r[3];
            ldm_x4_trans(r, av_lo + swz(row, c16));
            Bvl[2*a][0] = r[0]; Bvl[2*a][1] = r[1];
            Bvl[2*a+1][0] = r[2]; Bvl[2*a+1][1] = r[3];
        }
        #pragma unroll
        for (int nt = 0; nt < 4; nt++) mma16816(o[nt], aPh, Bvh[nt]);
        #pragma unroll
        for (int nt = 0; nt < 4; nt++) mma16816(o[nt], aPl, Bvh[nt]);
        #pragma unroll
        for (int nt = 0; nt < 4; nt++) mma16816(o[nt], aPh, Bvl[nt]);
    }

    // ---- epilogue: normalize, split, stage in smem, coalesced store ---------
    __syncthreads();   // all warps done reading q tiles; reuse as stage
    __nv_bfloat16* st_hi = sq_hi;  // [64][32], 64B rows
    __nv_bfloat16* st_lo = sq_lo;
    {
        int r0 = 16 * wid + (lane >> 2);
        int cb = (lane & 3) * 2;
        #pragma unroll
        for (int nt = 0; nt < 4; nt++) {
            uint32_t h01, l01, h23, l23;
            split2_pack(o[nt][0] * inv0, o[nt][1] * inv0, h01, l01);
            split2_pack(o[nt][2] * inv1, o[nt][3] * inv1, h23, l23);
            int d = nt * 8 + cb;
            *reinterpret_cast<uint32_t*>(&st_hi[r0 * 32 + d])       = h01;
            *reinterpret_cast<uint32_t*>(&st_lo[r0 * 32 + d])       = l01;
            *reinterpret_cast<uint32_t*>(&st_hi[(r0 + 8) * 32 + d]) = h23;
            *reinterpret_cast<uint32_t*>(&st_lo[(r0 + 8) * 32 + d]) = l23;
        }
    }
    __syncthreads();
    {
        int tok  = tid >> 1;
        int half = tid & 1;
        int wsh = tok >> 3, wsw = tok & 7;
        int pixo = (hh * 8 + wsh) * 64 + ww * 8 + wsw;
        size_t off = ((size_t)b * HW + pixo) * CCH + head * DHEAD + half * 16;
        const uint4* sh = reinterpret_cast<const uint4*>(&st_hi[tok * 32 + half * 16]);
        const uint4* sl = reinterpret_cast<const uint4*>(&st_lo[tok * 32 + half * 16]);
        uint4* dh = reinterpret_cast<uint4*>(g_o_hi + off);
        uint4* dl = reinterpret_cast<uint4*>(g_o_lo + off);
        dh[0] = sh[0]; dh[1] = sh[1];
        dl[0] = sl[0]; dl[1] = sl[1];
    }
}

// ---------------------------------------------------------------------------
extern "C" void kernel_launch(void* const* d_in, const int* in_sizes, int n_in,
                              void* d_out, int out_size)
{
    const float* x      = (const float*)d_in[0];
    const float* w_qkv  = (const float*)d_in[1];
    const float* b_qkv  = (const float*)d_in[2];
    const float* w_proj = (const float*)d_in[3];
    const float* b_proj = (const float*)d_in[4];
    float* out = (float*)d_out;
    (void)in_sizes; (void)n_in; (void)out_size;

    cudaFuncSetAttribute(gemm_mma_kernel<0>,
                         cudaFuncAttributeMaxDynamicSharedMemorySize, GEMM_SMEM);
    cudaFuncSetAttribute(gemm_mma_kernel<1>,
                         cudaFuncAttributeMaxDynamicSharedMemorySize, GEMM_SMEM);

    weight_split_kernel<<<(QKV_C * CCH + 255) / 256, 256>>>(w_qkv, w_proj);

    dim3 gT(HW / 32, CCH / 32, BATCH);
    transpose_split_kernel<<<gT, 256>>>(x);

    dim3 g1(HW / 128, QKV_C / 128, BATCH);
    gemm_mma_kernel<0><<<g1, 256, GEMM_SMEM>>>(b_qkv, nullptr);

    dim3 gA(64, NHEADS, BATCH);
    attn_mma_kernel<<<gA, 128>>>();

    dim3 g2(HW / 128, CCH / 128, BATCH);
    gemm_mma_kernel<1><<<g2, 256, GEMM_SMEM>>>(b_proj, out);
}

// round 5
// speedup vs baseline: 3.7207x; 1.4325x over previous
#include <cuda_runtime.h>
#include <cuda_bf16.h>
#include <cuda_fp16.h>
#include <cstdint>

// Problem constants
#define BATCH  16
#define CCH    384
#define HW     4096
#define NHEADS 12
#define DHEAD  32
#define QKV_C  1152

#define BK     32
#define NCHUNK (CCH / BK)   // 12

// ---------------------------------------------------------------------------
// Device-global scratch (no cudaMalloc allowed)
// ---------------------------------------------------------------------------
__device__ float g_qkv[(size_t)BATCH * HW * QKV_C];                  // [b][pix][3C]
__device__ __align__(256) __half g_xt_hi[(size_t)BATCH * HW * CCH];  // x^T [b][pix][c]
__device__ __align__(256) __half g_xt_lo[(size_t)BATCH * HW * CCH];
__device__ __align__(256) __half g_o_hi[(size_t)BATCH * HW * CCH];   // attn out
__device__ __align__(256) __half g_o_lo[(size_t)BATCH * HW * CCH];
__device__ __align__(256) __half g_wq_h[QKV_C * CCH];                // weights fp16
__device__ __align__(256) __half g_wp_h[CCH * CCH];

// ---------------------------------------------------------------------------
// Helpers
// ---------------------------------------------------------------------------
__device__ __forceinline__ uint32_t smem_u32(const void* p) {
    uint32_t a;
    asm("{ .reg .u64 t; cvta.to.shared.u64 t, %1; cvt.u32.u64 %0, t; }"
        : "=r"(a) : "l"(p));
    return a;
}

// fp16 hi/lo split of one float
__device__ __forceinline__ void split_h(float v, __half& h, __half& l) {
    h = __float2half_rn(v);
    l = __float2half_rn(v - __half2float(h));
}

// bf16 hi/lo split of 2 floats packed into 2 u32 (low half = first value)
__device__ __forceinline__ void split2_pack(float a, float b, uint32_t& hi, uint32_t& lo) {
    __nv_bfloat16 ha = __float2bfloat16(a), hb = __float2bfloat16(b);
    float ra = a - __bfloat162float(ha), rb = b - __bfloat162float(hb);
    __nv_bfloat16 la = __float2bfloat16(ra), lb = __float2bfloat16(rb);
    uint16_t uha = *reinterpret_cast<uint16_t*>(&ha);
    uint16_t uhb = *reinterpret_cast<uint16_t*>(&hb);
    uint16_t ula = *reinterpret_cast<uint16_t*>(&la);
    uint16_t ulb = *reinterpret_cast<uint16_t*>(&lb);
    hi = (uint32_t)uha | ((uint32_t)uhb << 16);
    lo = (uint32_t)ula | ((uint32_t)ulb << 16);
}

// fp16 hi/lo split of 2 floats packed into 2 u32
__device__ __forceinline__ void split2_pack_h(float a, float b, uint32_t& hi, uint32_t& lo) {
    __half ha = __float2half_rn(a), hb = __float2half_rn(b);
    float ra = a - __half2float(ha), rb = b - __half2float(hb);
    __half la = __float2half_rn(ra), lb = __float2half_rn(rb);
    uint16_t uha = *reinterpret_cast<uint16_t*>(&ha);
    uint16_t uhb = *reinterpret_cast<uint16_t*>(&hb);
    uint16_t ula = *reinterpret_cast<uint16_t*>(&la);
    uint16_t ulb = *reinterpret_cast<uint16_t*>(&lb);
    hi = (uint32_t)uha | ((uint32_t)uhb << 16);
    lo = (uint32_t)ula | ((uint32_t)ulb << 16);
}

// smem tile: rows of 32 x 16-bit (64B/row), 16B chunks swizzled for ldmatrix
__device__ __forceinline__ uint32_t swz(uint32_t row, uint32_t c16) {
    return row * 64u + ((c16 ^ ((row >> 1) & 3u)) * 16u);
}

__device__ __forceinline__ void ldm_x4(uint32_t* r, uint32_t addr) {
    asm volatile("ldmatrix.sync.aligned.m8n8.x4.shared.b16 {%0,%1,%2,%3}, [%4];"
                 : "=r"(r[0]), "=r"(r[1]), "=r"(r[2]), "=r"(r[3]) : "r"(addr));
}

__device__ __forceinline__ void ldm_x4_trans(uint32_t* r, uint32_t addr) {
    asm volatile("ldmatrix.sync.aligned.m8n8.x4.trans.shared.b16 {%0,%1,%2,%3}, [%4];"
                 : "=r"(r[0]), "=r"(r[1]), "=r"(r[2]), "=r"(r[3]) : "r"(addr));
}

__device__ __forceinline__ void mma16816(float* c, const uint32_t* a, const uint32_t* b) {
    asm volatile(
        "mma.sync.aligned.m16n8k16.row.col.f32.bf16.bf16.f32 "
        "{%0,%1,%2,%3}, {%4,%5,%6,%7}, {%8,%9}, {%0,%1,%2,%3};"
        : "+f"(c[0]), "+f"(c[1]), "+f"(c[2]), "+f"(c[3])
        : "r"(a[0]), "r"(a[1]), "r"(a[2]), "r"(a[3]), "r"(b[0]), "r"(b[1]));
}

__device__ __forceinline__ void mma16816h(float* c, const uint32_t* a, const uint32_t* b) {
    asm volatile(
        "mma.sync.aligned.m16n8k16.row.col.f32.f16.f16.f32 "
        "{%0,%1,%2,%3}, {%4,%5,%6,%7}, {%8,%9}, {%0,%1,%2,%3};"
        : "+f"(c[0]), "+f"(c[1]), "+f"(c[2]), "+f"(c[3])
        : "r"(a[0]), "r"(a[1]), "r"(a[2]), "r"(a[3]), "r"(b[0]), "r"(b[1]));
}

#define CP_ASYNC16(dst, src) \
    asm volatile("cp.async.cg.shared.global [%0], [%1], 16;" :: "r"(dst), "l"(src))
#define CP_COMMIT() asm volatile("cp.async.commit_group;")
#define CP_WAIT0()  asm volatile("cp.async.wait_group 0;")
#define CP_WAIT1()  asm volatile("cp.async.wait_group 1;")

// load one 128x32 fp16 tile (row stride CCH) into swizzled smem via cp.async
__device__ __forceinline__ void load_tile_async(const __half* __restrict__ src,
                                                int row0, int k0, uint32_t dst, int tid) {
    #pragma unroll
    for (int j = 0; j < 2; j++) {
        int c   = tid + j * 256;
        int row = c >> 2, c16 = c & 3;
        const __half* g = src + (size_t)(row0 + row) * CCH + k0 + c16 * 8;
        CP_ASYNC16(dst + swz((uint32_t)row, (uint32_t)c16), g);
    }
}

// ---------------------------------------------------------------------------
// Kernel 1: transpose x [b][c][pix] -> fp16 hi/lo [b][pix][c]
// ---------------------------------------------------------------------------
__global__ __launch_bounds__(256) void transpose_split_kernel(const float* __restrict__ x)
{
    __shared__ float t[32][33];
    const int b  = blockIdx.z;
    const int p0 = blockIdx.x * 32;
    const int c0 = blockIdx.y * 32;
    const int tx = threadIdx.x & 31;
    const int ty = threadIdx.x >> 5;

    const float* xb = x + (size_t)b * CCH * HW;
    #pragma unroll
    for (int i = 0; i < 4; i++)
        t[ty + i * 8][tx] = xb[(size_t)(c0 + ty + i * 8) * HW + p0 + tx];
    __syncthreads();

    #pragma unroll
    for (int i = 0; i < 4; i++) {
        int p = p0 + ty + i * 8;
        int c = c0 + tx;
        __half h, l;
        split_h(t[tx][ty + i * 8], h, l);
        size_t idx = ((size_t)b * HW + p) * CCH + c;
        g_xt_hi[idx] = h;
        g_xt_lo[idx] = l;
    }
}

// ---------------------------------------------------------------------------
// Kernel 2: weights -> fp16 (single rounding)
// ---------------------------------------------------------------------------
__global__ void weight_half_kernel(const float* __restrict__ wq,
                                   const float* __restrict__ wp)
{
    int i = blockIdx.x * blockDim.x + threadIdx.x;
    if (i < QKV_C * CCH) g_wq_h[i] = __float2half_rn(wq[i]);
    if (i < CCH * CCH)   g_wp_h[i] = __float2half_rn(wp[i]);
}

// ---------------------------------------------------------------------------
// Tensor-core GEMM (fp16 mma, 2-pass A-split, fp32 accumulate)
// D[pix(128)][och(128)] = (Ah+Al)[pix][cch] . Bh[och][cch]^T
// 3-stage cp.async pipeline. Stage = Ah(8K) Al(8K) B(8K) = 24KB.
// G==0: A = g_xt, B = w_qkv -> g_qkv [b][pix][1152]
// G==1: A = g_o,  B = w_proj -> out  [b][och][4096]
// ---------------------------------------------------------------------------
#define STAGE_BYTES 24576
#define GEMM_SMEM   (3 * STAGE_BYTES)   // 73728

template<int G>
__global__ __launch_bounds__(256) void gemm_mma_kernel(const float* __restrict__ bias,
                                                       float* __restrict__ out_base)
{
    extern __shared__ __align__(128) char smem[];
    const uint32_t sbase = smem_u32(smem);
    const int tid = threadIdx.x, wid = tid >> 5, lane = tid & 31;
    const int warp_m = wid & 3;
    const int warp_n = wid >> 2;

    const int b  = blockIdx.z;
    const int n0 = blockIdx.x * 128;   // och tile (x fastest -> A reuse in L2)
    const int m0 = blockIdx.y * 128;   // pixel tile

    const __half* Ahi = (G == 0 ? g_xt_hi : g_o_hi) + (size_t)b * HW * CCH;
    const __half* Alo = (G == 0 ? g_xt_lo : g_o_lo) + (size_t)b * HW * CCH;
    const __half* Bh  = (G == 0 ? g_wq_h  : g_wp_h);

    float acc[2][8][4] = {};

    // prologue: chunks 0,1
    #pragma unroll
    for (int i = 0; i < 2; i++) {
        const uint32_t sb = sbase + i * STAGE_BYTES;
        load_tile_async(Ahi, m0, i * BK, sb + 0,     tid);
        load_tile_async(Alo, m0, i * BK, sb + 8192,  tid);
        load_tile_async(Bh,  n0, i * BK, sb + 16384, tid);
        CP_COMMIT();
    }
    CP_WAIT1();            // chunk 0 ready
    __syncthreads();

    const int lrow = lane & 7;
    const int lblk = lane >> 3;

    #pragma unroll 1
    for (int i = 0; i < NCHUNK; i++) {
        if (i + 2 < NCHUNK) {
            const uint32_t nb = sbase + ((i + 2) % 3) * STAGE_BYTES;
            const int k0 = (i + 2) * BK;
            load_tile_async(Ahi, m0, k0, nb + 0,     tid);
            load_tile_async(Alo, m0, k0, nb + 8192,  tid);
            load_tile_async(Bh,  n0, k0, nb + 16384, tid);
            CP_COMMIT();
        }

        const uint32_t sAh = sbase + (i % 3) * STAGE_BYTES;
        const uint32_t sAl = sAh + 8192;
        const uint32_t sB  = sAh + 16384;

        #pragma unroll
        for (int ks = 0; ks < 2; ks++) {
            uint32_t Af[2][4], Al4[2][4];
            #pragma unroll
            for (int mt = 0; mt < 2; mt++) {
                uint32_t row = (uint32_t)(warp_m * 32 + mt * 16 + (lblk & 1) * 8 + lrow);
                uint32_t c16 = (uint32_t)(ks * 2 + (lblk >> 1));
                uint32_t off = swz(row, c16);
                ldm_x4(Af[mt],  sAh + off);
                ldm_x4(Al4[mt], sAl + off);
            }
            uint32_t Bf[8][2];
            #pragma unroll
            for (int np = 0; np < 4; np++) {
                uint32_t row = (uint32_t)(warp_n * 64 + np * 16 + (lblk >> 1) * 8 + lrow);
                uint32_t c16 = (uint32_t)(ks * 2 + (lblk & 1));
                uint32_t r[4];
                ldm_x4(r, sB + swz(row, c16));
                Bf[np*2][0] = r[0]; Bf[np*2][1] = r[1];
                Bf[np*2+1][0] = r[2]; Bf[np*2+1][1] = r[3];
            }
            #pragma unroll
            for (int mt = 0; mt < 2; mt++)
                #pragma unroll
                for (int nt = 0; nt < 8; nt++)
                    mma16816h(acc[mt][nt], Af[mt], Bf[nt]);
            #pragma unroll
            for (int mt = 0; mt < 2; mt++)
                #pragma unroll
                for (int nt = 0; nt < 8; nt++)
                    mma16816h(acc[mt][nt], Al4[mt], Bf[nt]);
        }

        if (i + 2 < NCHUNK)      CP_WAIT1();
        else if (i + 1 < NCHUNK) CP_WAIT0();
        __syncthreads();
    }

    // ------------------- epilogue (smem-staged, coalesced) -------------------
    if (G == 0) {
        constexpr int PAD = 68;
        float* st = reinterpret_cast<float*>(smem);
        float* outb = g_qkv + (size_t)b * HW * QKV_C;
        #pragma unroll 1
        for (int h = 0; h < 2; h++) {
            __syncthreads();
            if (warp_n == h) {
                #pragma unroll
                for (int mt = 0; mt < 2; mt++)
                    #pragma unroll
                    for (int nt = 0; nt < 8; nt++) {
                        int ml = warp_m * 32 + mt * 16 + (lane >> 2);
                        int nl = nt * 8 + (lane & 3) * 2;
                        st[ml * PAD + nl]           = acc[mt][nt][0];
                        st[ml * PAD + nl + 1]       = acc[mt][nt][1];
                        st[(ml + 8) * PAD + nl]     = acc[mt][nt][2];
                        st[(ml + 8) * PAD + nl + 1] = acc[mt][nt][3];
                    }
            }
            __syncthreads();
            #pragma unroll
            for (int j = 0; j < 8; j++) {
                int fi  = tid + j * 256;
                int row = fi >> 4;
                int c4  = (fi & 15) * 4;
                int n   = n0 + h * 64 + c4;
                float4 v  = *reinterpret_cast<float4*>(&st[row * PAD + c4]);
                float4 bb = *reinterpret_cast<const float4*>(&bias[n]);
                v.x += bb.x; v.y += bb.y; v.z += bb.z; v.w += bb.w;
                *reinterpret_cast<float4*>(&outb[(size_t)(m0 + row) * QKV_C + n]) = v;
            }
        }
    } else {
        constexpr int PAD = 132;
        float* st = reinterpret_cast<float*>(smem);
        float* outb = out_base + (size_t)b * CCH * HW;
        #pragma unroll 1
        for (int h = 0; h < 2; h++) {
            __syncthreads();
            if (warp_n == h) {
                #pragma unroll
                for (int mt = 0; mt < 2; mt++)
                    #pragma unroll
                    for (int nt = 0; nt < 8; nt++) {
                        int ml = warp_m * 32 + mt * 16 + (lane >> 2);
                        int nl = nt * 8 + (lane & 3) * 2;
                        st[nl * PAD + ml]           = acc[mt][nt][0];
                        st[(nl + 1) * PAD + ml]     = acc[mt][nt][1];
                        st[nl * PAD + ml + 8]       = acc[mt][nt][2];
                        st[(nl + 1) * PAD + ml + 8] = acc[mt][nt][3];
                    }
            }
            __syncthreads();
            #pragma unroll
            for (int j = 0; j < 8; j++) {
                int fi  = tid + j * 256;
                int row = fi >> 5;
                int c4  = (fi & 31) * 4;
                int och = n0 + h * 64 + row;
                float4 v = *reinterpret_cast<float4*>(&st[row * PAD + c4]);
                float bi = bias[och];
                v.x += bi; v.y += bi; v.z += bi; v.w += bi;
                *reinterpret_cast<float4*>(&outb[(size_t)och * HW + m0 + c4]) = v;
            }
        }
    }
}

// ---------------------------------------------------------------------------
// Attention via mma.sync (3-pass bf16 split), 1 block = (b, head, window).
// 4 warps; warp w owns query rows 16w..16w+15 (m16). Strided windows.
// ---------------------------------------------------------------------------
__global__ __launch_bounds__(128) void attn_mma_kernel()
{
    __shared__ __align__(128) __nv_bfloat16 sq_hi[64 * 32];
    __shared__ __align__(128) __nv_bfloat16 sq_lo[64 * 32];
    __shared__ __align__(128) __nv_bfloat16 sk_hi[64 * 32];
    __shared__ __align__(128) __nv_bfloat16 sk_lo[64 * 32];
    __shared__ __align__(128) __nv_bfloat16 sv_hi[64 * 32];
    __shared__ __align__(128) __nv_bfloat16 sv_lo[64 * 32];

    const int wi   = blockIdx.x;
    const int head = blockIdx.y;
    const int b    = blockIdx.z;
    const int hh   = wi >> 3;
    const int ww   = wi & 7;
    const int tid  = threadIdx.x;
    const int wid  = tid >> 5;
    const int lane = tid & 31;

    const uint32_t aq_hi = smem_u32(sq_hi), aq_lo = smem_u32(sq_lo);
    const uint32_t ak_hi = smem_u32(sk_hi), ak_lo = smem_u32(sk_lo);
    const uint32_t av_hi = smem_u32(sv_hi), av_lo = smem_u32(sv_lo);

    const float* base = g_qkv + (size_t)b * HW * QKV_C + (size_t)head * DHEAD;
    const float SCALE = 0.17677669529663687f;

    #pragma unroll 1
    for (int it = 0; it < 12; it++) {
        int f4  = tid + it * 128;
        int ten = f4 >> 9;             // 0=q 1=k 2=v
        int rem = f4 & 511;
        int tok = rem >> 3;
        int c4  = rem & 7;
        int wsh = tok >> 3, wsw = tok & 7;
        int pix = (wsh * 8 + hh) * 64 + wsw * 8 + ww;
        float4 v = *reinterpret_cast<const float4*>(
            base + (size_t)pix * QKV_C + ten * CCH + c4 * 4);
        float s = (ten == 0) ? SCALE : 1.0f;
        uint32_t h01, l01, h23, l23;
        split2_pack(v.x * s, v.y * s, h01, l01);
        split2_pack(v.z * s, v.w * s, h23, l23);
        uint32_t hbase = (ten == 0) ? aq_hi : (ten == 1) ? ak_hi : av_hi;
        uint32_t lbase = (ten == 0) ? aq_lo : (ten == 1) ? ak_lo : av_lo;
        uint32_t off = swz((uint32_t)tok, (uint32_t)(c4 >> 1)) + (uint32_t)(c4 & 1) * 8;
        asm volatile("st.shared.v2.b32 [%0], {%1,%2};" :: "r"(hbase + off), "r"(h01), "r"(h23));
        asm volatile("st.shared.v2.b32 [%0], {%1,%2};" :: "r"(lbase + off), "r"(l01), "r"(l23));
    }
    __syncthreads();

    const int lrow = lane & 7;
    const int lblk = lane >> 3;

    // ---- S = Q K^T (scaled), 3-pass split -----------------------------------
    float acc[8][4] = {};
    #pragma unroll
    for (int ks = 0; ks < 2; ks++) {
        uint32_t Ah[4], Al[4];
        {
            uint32_t row = (uint32_t)(wid * 16 + (lblk & 1) * 8 + lrow);
            uint32_t c16 = (uint32_t)(ks * 2 + (lblk >> 1));
            uint32_t off = swz(row, c16);
            ldm_x4(Ah, aq_hi + off);
            ldm_x4(Al, aq_lo + off);
        }
        uint32_t Bh[8][2], Bl[8][2];
        #pragma unroll
        for (int np = 0; np < 4; np++) {
            uint32_t row = (uint32_t)(np * 16 + (lblk >> 1) * 8 + lrow);
            uint32_t c16 = (uint32_t)(ks * 2 + (lblk & 1));
            uint32_t r[4];
            ldm_x4(r, ak_hi + swz(row, c16));
            Bh[np*2][0] = r[0]; Bh[np*2][1] = r[1];
            Bh[np*2+1][0] = r[2]; Bh[np*2+1][1] = r[3];
            ldm_x4(r, ak_lo + swz(row, c16));
            Bl[np*2][0] = r[0]; Bl[np*2][1] = r[1];
            Bl[np*2+1][0] = r[2]; Bl[np*2+1][1] = r[3];
        }
        #pragma unroll
        for (int nt = 0; nt < 8; nt++) mma16816(acc[nt], Ah, Bh[nt]);
        #pragma unroll
        for (int nt = 0; nt < 8; nt++) mma16816(acc[nt], Al, Bh[nt]);
        #pragma unroll
        for (int nt = 0; nt < 8; nt++) mma16816(acc[nt], Ah, Bl[nt]);
    }

    // ---- softmax in registers ----------------------------------------------
    float mx0 = -1e30f, mx1 = -1e30f;
    #pragma unroll
    for (int nt = 0; nt < 8; nt++) {
        mx0 = fmaxf(mx0, fmaxf(acc[nt][0], acc[nt][1]));
        mx1 = fmaxf(mx1, fmaxf(acc[nt][2], acc[nt][3]));
    }
    #pragma unroll
    for (int d = 1; d <= 2; d <<= 1) {
        mx0 = fmaxf(mx0, __shfl_xor_sync(0xffffffffu, mx0, d));
        mx1 = fmaxf(mx1, __shfl_xor_sync(0xffffffffu, mx1, d));
    }
    float s0 = 0.f, s1 = 0.f;
    #pragma unroll
    for (int nt = 0; nt < 8; nt++) {
        acc[nt][0] = __expf(acc[nt][0] - mx0);
        acc[nt][1] = __expf(acc[nt][1] - mx0);
        acc[nt][2] = __expf(acc[nt][2] - mx1);
        acc[nt][3] = __expf(acc[nt][3] - mx1);
        s0 += acc[nt][0] + acc[nt][1];
        s1 += acc[nt][2] + acc[nt][3];
    }
    #pragma unroll
    for (int d = 1; d <= 2; d <<= 1) {
        s0 += __shfl_xor_sync(0xffffffffu, s0, d);
        s1 += __shfl_xor_sync(0xffffffffu, s1, d);
    }
    const float inv0 = 1.f / s0, inv1 = 1.f / s1;

    // ---- O = P V, P packed straight from accumulators (3-pass bf16) ---------
    float o[4][4] = {};
    #pragma unroll
    for (int j = 0; j < 4; j++) {
        uint32_t aPh[4], aPl[4];
        split2_pack(acc[2*j][0],   acc[2*j][1],   aPh[0], aPl[0]);
        split2_pack(acc[2*j][2],   acc[2*j][3],   aPh[1], aPl[1]);
        split2_pack(acc[2*j+1][0], acc[2*j+1][1], aPh[2], aPl[2]);
        split2_pack(acc[2*j+1][2], acc[2*j+1][3], aPh[3], aPl[3]);

        uint32_t Bvh[4][2], Bvl[4][2];
        #pragma unroll
        for (int a = 0; a < 2; a++) {
            uint32_t row = (uint32_t)(16 * j + lrow + (lblk & 1) * 8);
            uint32_t c16 = (uint32_t)(2 * a + (lblk >> 1));
            uint32_t r[4];
            ldm_x4_trans(r, av_hi + swz(row, c16));
            Bvh[2*a][0] = r[0]; Bvh[2*a][1] = r[1];
            Bvh[2*a+1][0] = r[2]; Bvh[2*a+1][1] = r[3];
            ldm_x4_trans(r, av_lo + swz(row, c16));
            Bvl[2*a][0] = r[0]; Bvl[2*a][1] = r[1];
            Bvl[2*a+1][0] = r[2]; Bvl[2*a+1][1] = r[3];
        }
        #pragma unroll
        for (int nt = 0; nt < 4; nt++) mma16816(o[nt], aPh, Bvh[nt]);
        #pragma unroll
        for (int nt = 0; nt < 4; nt++) mma16816(o[nt], aPl, Bvh[nt]);
        #pragma unroll
        for (int nt = 0; nt < 4; nt++) mma16816(o[nt], aPh, Bvl[nt]);
    }

    // ---- epilogue: normalize, fp16-split, stage in smem, coalesced store ----
    __syncthreads();
    __nv_bfloat16* st_hi = sq_hi;   // byte staging (contents are fp16)
    __nv_bfloat16* st_lo = sq_lo;
    {
        int r0 = 16 * wid + (lane >> 2);
        int cb = (lane & 3) * 2;
        #pragma unroll
        for (int nt = 0; nt < 4; nt++) {
            uint32_t h01, l01, h23, l23;
            split2_pack_h(o[nt][0] * inv0, o[nt][1] * inv0, h01, l01);
            split2_pack_h(o[nt][2] * inv1, o[nt][3] * inv1, h23, l23);
            int d = nt * 8 + cb;
            *reinterpret_cast<uint32_t*>(&st_hi[r0 * 32 + d])       = h01;
            *reinterpret_cast<uint32_t*>(&st_lo[r0 * 32 + d])       = l01;
            *reinterpret_cast<uint32_t*>(&st_hi[(r0 + 8) * 32 + d]) = h23;
            *reinterpret_cast<uint32_t*>(&st_lo[(r0 + 8) * 32 + d]) = l23;
        }
    }
    __syncthreads();
    {
        int tok  = tid >> 1;
        int half = tid & 1;
        int wsh = tok >> 3, wsw = tok & 7;
        int pixo = (hh * 8 + wsh) * 64 + ww * 8 + wsw;
        size_t off = ((size_t)b * HW + pixo) * CCH + head * DHEAD + half * 16;
        const uint4* sh = reinterpret_cast<const uint4*>(&st_hi[tok * 32 + half * 16]);
        const uint4* sl = reinterpret_cast<const uint4*>(&st_lo[tok * 32 + half * 16]);
        uint4* dh = reinterpret_cast<uint4*>(g_o_hi + off);
        uint4* dl = reinterpret_cast<uint4*>(g_o_lo + off);
        dh[0] = sh[0]; dh[1] = sh[1];
        dl[0] = sl[0]; dl[1] = sl[1];
    }
}

// ---------------------------------------------------------------------------
extern "C" void kernel_launch(void* const* d_in, const int* in_sizes, int n_in,
                              void* d_out, int out_size)
{
    const float* x      = (const float*)d_in[0];
    const float* w_qkv  = (const float*)d_in[1];
    const float* b_qkv  = (const float*)d_in[2];
    const float* w_proj = (const float*)d_in[3];
    const float* b_proj = (const float*)d_in[4];
    float* out = (float*)d_out;
    (void)in_sizes; (void)n_in; (void)out_size;

    cudaFuncSetAttribute(gemm_mma_kernel<0>,
                         cudaFuncAttributeMaxDynamicSharedMemorySize, GEMM_SMEM);
    cudaFuncSetAttribute(gemm_mma_kernel<1>,
                         cudaFuncAttributeMaxDynamicSharedMemorySize, GEMM_SMEM);

    weight_half_kernel<<<(QKV_C * CCH + 255) / 256, 256>>>(w_qkv, w_proj);

    dim3 gT(HW / 32, CCH / 32, BATCH);
    transpose_split_kernel<<<gT, 256>>>(x);

    dim3 g1(QKV_C / 128, HW / 128, BATCH);   // n fastest -> A-tile L2 reuse
    gemm_mma_kernel<0><<<g1, 256, GEMM_SMEM>>>(b_qkv, nullptr);

    dim3 gA(64, NHEADS, BATCH);
    attn_mma_kernel<<<gA, 128>>>();

    dim3 g2(CCH / 128, HW / 128, BATCH);
    gemm_mma_kernel<1><<<g2, 256, GEMM_SMEM>>>(b_proj, out);
}

// round 7
// speedup vs baseline: 6.4672x; 1.7381x over previous
#include <cuda_runtime.h>
#include <cuda_fp16.h>
#include <cstdint>

// Problem constants
#define BATCH  16
#define CCH    384
#define HW     4096
#define NHEADS 12
#define DHEAD  32
#define QKV_C  1152

#define BK     32
#define NCHUNK (CCH / BK)   // 12

// ---------------------------------------------------------------------------
// Device-global scratch (no cudaMalloc allowed)
// ---------------------------------------------------------------------------
__device__ __align__(256) __half g_qkv[(size_t)BATCH * HW * QKV_C]; // fp16, q pre-scaled
__device__ __align__(256) __half g_xt[(size_t)BATCH * HW * CCH];    // x^T fp16 [b][pix][c]
__device__ __align__(256) __half g_o [(size_t)BATCH * HW * CCH];    // attn out fp16
__device__ __align__(256) __half g_wq_h[QKV_C * CCH];
__device__ __align__(256) __half g_wp_h[CCH * CCH];

// ---------------------------------------------------------------------------
// Helpers
// ---------------------------------------------------------------------------
__device__ __forceinline__ uint32_t smem_u32(const void* p) {
    uint32_t a;
    asm("{ .reg .u64 t; cvta.to.shared.u64 t, %1; cvt.u32.u64 %0, t; }"
        : "=r"(a) : "l"(p));
    return a;
}

__device__ __forceinline__ uint32_t pack_half2(float a, float b) {
    __half ha = __float2half_rn(a), hb = __float2half_rn(b);
    uint16_t ua = *reinterpret_cast<uint16_t*>(&ha);
    uint16_t ub = *reinterpret_cast<uint16_t*>(&hb);
    return (uint32_t)ua | ((uint32_t)ub << 16);
}

// fp16 hi/lo split of 2 floats packed into 2 u32
__device__ __forceinline__ void split2_pack_h(float a, float b, uint32_t& hi, uint32_t& lo) {
    __half ha = __float2half_rn(a), hb = __float2half_rn(b);
    float ra = a - __half2float(ha), rb = b - __half2float(hb);
    __half la = __float2half_rn(ra), lb = __float2half_rn(rb);
    uint16_t uha = *reinterpret_cast<uint16_t*>(&ha);
    uint16_t uhb = *reinterpret_cast<uint16_t*>(&hb);
    uint16_t ula = *reinterpret_cast<uint16_t*>(&la);
    uint16_t ulb = *reinterpret_cast<uint16_t*>(&lb);
    hi = (uint32_t)uha | ((uint32_t)uhb << 16);
    lo = (uint32_t)ula | ((uint32_t)ulb << 16);
}

// smem tile: rows of 32 x 16-bit (64B/row), 16B chunks swizzled for ldmatrix
__device__ __forceinline__ uint32_t swz(uint32_t row, uint32_t c16) {
    return row * 64u + ((c16 ^ ((row >> 1) & 3u)) * 16u);
}

__device__ __forceinline__ void ldm_x4(uint32_t* r, uint32_t addr) {
    asm volatile("ldmatrix.sync.aligned.m8n8.x4.shared.b16 {%0,%1,%2,%3}, [%4];"
                 : "=r"(r[0]), "=r"(r[1]), "=r"(r[2]), "=r"(r[3]) : "r"(addr));
}

__device__ __forceinline__ void ldm_x4_trans(uint32_t* r, uint32_t addr) {
    asm volatile("ldmatrix.sync.aligned.m8n8.x4.trans.shared.b16 {%0,%1,%2,%3}, [%4];"
                 : "=r"(r[0]), "=r"(r[1]), "=r"(r[2]), "=r"(r[3]) : "r"(addr));
}

__device__ __forceinline__ void mma16816h(float* c, const uint32_t* a, const uint32_t* b) {
    asm volatile(
        "mma.sync.aligned.m16n8k16.row.col.f32.f16.f16.f32 "
        "{%0,%1,%2,%3}, {%4,%5,%6,%7}, {%8,%9}, {%0,%1,%2,%3};"
        : "+f"(c[0]), "+f"(c[1]), "+f"(c[2]), "+f"(c[3])
        : "r"(a[0]), "r"(a[1]), "r"(a[2]), "r"(a[3]), "r"(b[0]), "r"(b[1]));
}

#define CP_ASYNC16(dst, src) \
    asm volatile("cp.async.cg.shared.global [%0], [%1], 16;" :: "r"(dst), "l"(src))
#define CP_COMMIT() asm volatile("cp.async.commit_group;")
#define CP_WAIT0()  asm volatile("cp.async.wait_group 0;")
#define CP_WAIT1()  asm volatile("cp.async.wait_group 1;")

// load one 128x32 fp16 tile (row stride CCH) into swizzled smem via cp.async
__device__ __forceinline__ void load_tile_async(const __half* __restrict__ src,
                                                int row0, int k0, uint32_t dst, int tid) {
    #pragma unroll
    for (int j = 0; j < 2; j++) {
        int c   = tid + j * 256;
        int row = c >> 2, c16 = c & 3;
        const __half* g = src + (size_t)(row0 + row) * CCH + k0 + c16 * 8;
        CP_ASYNC16(dst + swz((uint32_t)row, (uint32_t)c16), g);
    }
}

// ---------------------------------------------------------------------------
// Kernel 1: transpose x [b][c][pix] -> fp16 [b][pix][c]
// ---------------------------------------------------------------------------
__global__ __launch_bounds__(256) void transpose_half_kernel(const float* __restrict__ x)
{
    __shared__ float t[32][33];
    const int b  = blockIdx.z;
    const int p0 = blockIdx.x * 32;
    const int c0 = blockIdx.y * 32;
    const int tx = threadIdx.x & 31;
    const int ty = threadIdx.x >> 5;

    const float* xb = x + (size_t)b * CCH * HW;
    #pragma unroll
    for (int i = 0; i < 4; i++)
        t[ty + i * 8][tx] = xb[(size_t)(c0 + ty + i * 8) * HW + p0 + tx];
    __syncthreads();

    #pragma unroll
    for (int i = 0; i < 4; i++) {
        int p = p0 + ty + i * 8;
        int c = c0 + tx;
        g_xt[((size_t)b * HW + p) * CCH + c] = __float2half_rn(t[tx][ty + i * 8]);
    }
}

// ---------------------------------------------------------------------------
// Kernel 2: weights -> fp16 (single rounding)
// ---------------------------------------------------------------------------
__global__ void weight_half_kernel(const float* __restrict__ wq,
                                   const float* __restrict__ wp)
{
    int i = blockIdx.x * blockDim.x + threadIdx.x;
    if (i < QKV_C * CCH) g_wq_h[i] = __float2half_rn(wq[i]);
    if (i < CCH * CCH)   g_wp_h[i] = __float2half_rn(wp[i]);
}

// ---------------------------------------------------------------------------
// Tensor-core GEMM (single-pass fp16 mma, fp32 accumulate)
// D[pix(128)][och(128)] = A[pix][cch] . B[och][cch]^T
// 3-stage cp.async pipeline; stage = A(8K) + B(8K) = 16KB.
// G==0: A = g_xt, B = w_qkv -> g_qkv fp16 [b][pix][1152], q cols pre-scaled
// G==1: A = g_o,  B = w_proj -> out  fp32 [b][och][4096]
// ---------------------------------------------------------------------------
#define STAGE_BYTES 16384
#define GEMM_SMEM   49152

template<int G>
__global__ __launch_bounds__(256) void gemm_mma_kernel(const float* __restrict__ bias,
                                                       float* __restrict__ out_base)
{
    extern __shared__ __align__(128) char smem[];
    const uint32_t sbase = smem_u32(smem);
    const int tid = threadIdx.x, wid = tid >> 5, lane = tid & 31;
    const int warp_m = wid & 3;
    const int warp_n = wid >> 2;

    const int b  = blockIdx.z;
    const int n0 = blockIdx.x * 128;   // och tile (x fastest -> A reuse in L2)
    const int m0 = blockIdx.y * 128;   // pixel tile

    const __half* A  = (G == 0 ? g_xt : g_o) + (size_t)b * HW * CCH;
    const __half* Bw = (G == 0 ? g_wq_h : g_wp_h);

    float acc[2][8][4] = {};

    #pragma unroll
    for (int i = 0; i < 2; i++) {
        const uint32_t sb = sbase + i * STAGE_BYTES;
        load_tile_async(A,  m0, i * BK, sb + 0,    tid);
        load_tile_async(Bw, n0, i * BK, sb + 8192, tid);
        CP_COMMIT();
    }
    CP_WAIT1();
    __syncthreads();

    const int lrow = lane & 7;
    const int lblk = lane >> 3;

    #pragma unroll 1
    for (int i = 0; i < NCHUNK; i++) {
        if (i + 2 < NCHUNK) {
            const uint32_t nb = sbase + ((i + 2) % 3) * STAGE_BYTES;
            const int k0 = (i + 2) * BK;
            load_tile_async(A,  m0, k0, nb + 0,    tid);
            load_tile_async(Bw, n0, k0, nb + 8192, tid);
            CP_COMMIT();
        }

        const uint32_t sA = sbase + (i % 3) * STAGE_BYTES;
        const uint32_t sB = sA + 8192;

        #pragma unroll
        for (int ks = 0; ks < 2; ks++) {
            uint32_t Af[2][4];
            #pragma unroll
            for (int mt = 0; mt < 2; mt++) {
                uint32_t row = (uint32_t)(warp_m * 32 + mt * 16 + (lblk & 1) * 8 + lrow);
                uint32_t c16 = (uint32_t)(ks * 2 + (lblk >> 1));
                ldm_x4(Af[mt], sA + swz(row, c16));
            }
            uint32_t Bf[8][2];
            #pragma unroll
            for (int np = 0; np < 4; np++) {
                uint32_t row = (uint32_t)(warp_n * 64 + np * 16 + (lblk >> 1) * 8 + lrow);
                uint32_t c16 = (uint32_t)(ks * 2 + (lblk & 1));
                uint32_t r[4];
                ldm_x4(r, sB + swz(row, c16));
                Bf[np*2][0] = r[0]; Bf[np*2][1] = r[1];
                Bf[np*2+1][0] = r[2]; Bf[np*2+1][1] = r[3];
            }
            #pragma unroll
            for (int mt = 0; mt < 2; mt++)
                #pragma unroll
                for (int nt = 0; nt < 8; nt++)
                    mma16816h(acc[mt][nt], Af[mt], Bf[nt]);
        }

        if (i + 2 < NCHUNK)      CP_WAIT1();
        else if (i + 1 < NCHUNK) CP_WAIT0();
        __syncthreads();
    }

    // ------------------- epilogue -------------------
    if (G == 0) {
        // fp16 out [b][pix][1152]; bias add; q columns (och<384) scaled.
        constexpr int PADH = 136;   // halves per staged row (272B, 16B-mult)
        const float SCALE = 0.17677669529663687f;
        __half* st = reinterpret_cast<__half*>(smem);   // [128][136]
        {
            #pragma unroll
            for (int mt = 0; mt < 2; mt++)
                #pragma unroll
                for (int nt = 0; nt < 8; nt++) {
                    int ml = warp_m * 32 + mt * 16 + (lane >> 2);
                    int nl = warp_n * 64 + nt * 8 + (lane & 3) * 2;
                    int och = n0 + nl;
                    float s  = (och < CCH) ? SCALE : 1.0f;
                    float b0 = bias[och], b1 = bias[och + 1];
                    *reinterpret_cast<uint32_t*>(&st[ml * PADH + nl]) =
                        pack_half2((acc[mt][nt][0] + b0) * s, (acc[mt][nt][1] + b1) * s);
                    *reinterpret_cast<uint32_t*>(&st[(ml + 8) * PADH + nl]) =
                        pack_half2((acc[mt][nt][2] + b0) * s, (acc[mt][nt][3] + b1) * s);
                }
        }
        __syncthreads();
        __half* outb = g_qkv + (size_t)b * HW * QKV_C;
        #pragma unroll
        for (int j = 0; j < 8; j++) {
            int fi  = tid + j * 256;          // 2048 chunks of 8 halves
            int row = fi >> 4;
            int c16 = fi & 15;
            uint4 v = *reinterpret_cast<uint4*>(&st[row * PADH + c16 * 8]);
            *reinterpret_cast<uint4*>(&outb[(size_t)(m0 + row) * QKV_C + n0 + c16 * 8]) = v;
        }
    } else {
        constexpr int PAD = 132;
        float* st = reinterpret_cast<float*>(smem);
        float* outb = out_base + (size_t)b * CCH * HW;
        #pragma unroll 1
        for (int h = 0; h < 2; h++) {
            __syncthreads();
            if (warp_n == h) {
                #pragma unroll
                for (int mt = 0; mt < 2; mt++)
                    #pragma unroll
                    for (int nt = 0; nt < 8; nt++) {
                        int ml = warp_m * 32 + mt * 16 + (lane >> 2);
                        int nl = nt * 8 + (lane & 3) * 2;
                        st[nl * PAD + ml]           = acc[mt][nt][0];
                        st[(nl + 1) * PAD + ml]     = acc[mt][nt][1];
                        st[nl * PAD + ml + 8]       = acc[mt][nt][2];
                        st[(nl + 1) * PAD + ml + 8] = acc[mt][nt][3];
                    }
            }
            __syncthreads();
            #pragma unroll
            for (int j = 0; j < 8; j++) {
                int fi  = tid + j * 256;
                int row = fi >> 5;
                int c4  = (fi & 31) * 4;
                int och = n0 + h * 64 + row;
                float4 v = *reinterpret_cast<float4*>(&st[row * PAD + c4]);
                float bi = bias[och];
                v.x += bi; v.y += bi; v.z += bi; v.w += bi;
                *reinterpret_cast<float4*>(&outb[(size_t)och * HW + m0 + c4]) = v;
            }
        }
    }
}

// ---------------------------------------------------------------------------
// Attention: 1 block = (b, head, window), 4 warps. All-fp16 operands.
// q pre-scaled by producer. S single-pass; P·V: P hi/lo 2-pass, V single.
// Strided windows (faithful to reference).
// ---------------------------------------------------------------------------
__global__ __launch_bounds__(128) void attn_mma_kernel()
{
    __shared__ __align__(128) __half sq[64 * 32];
    __shared__ __align__(128) __half sk[64 * 32];
    __shared__ __align__(128) __half sv[64 * 32];

    const int wi   = blockIdx.x;
    const int head = blockIdx.y;
    const int b    = blockIdx.z;
    const int hh   = wi >> 3;
    const int ww   = wi & 7;
    const int tid  = threadIdx.x;
    const int wid  = tid >> 5;
    const int lane = tid & 31;

    const uint32_t aq = smem_u32(sq), ak = smem_u32(sk), av = smem_u32(sv);

    const __half* base = g_qkv + (size_t)b * HW * QKV_C + (size_t)head * DHEAD;

    // ---- cp.async q,k,v straight into swizzled smem -------------------------
    #pragma unroll
    for (int it = 0; it < 6; it++) {
        int e   = tid + it * 128;
        int ten = e >> 8;              // 0=q 1=k 2=v
        int rem = e & 255;
        int tok = rem >> 2;
        int c16 = rem & 3;
        int wsh = tok >> 3, wsw = tok & 7;
        int pix = (wsh * 8 + hh) * 64 + wsw * 8 + ww;
        const __half* g = base + (size_t)pix * QKV_C + ten * CCH + c16 * 8;
        uint32_t dst = (ten == 0 ? aq : ten == 1 ? ak : av) + swz((uint32_t)tok, (uint32_t)c16);
        CP_ASYNC16(dst, g);
    }
    CP_COMMIT();
    CP_WAIT0();
    __syncthreads();

    const int lrow = lane & 7;
    const int lblk = lane >> 3;

    // ---- S = Q K^T (q pre-scaled), single-pass fp16 -------------------------
    float acc[8][4] = {};
    #pragma unroll
    for (int ks = 0; ks < 2; ks++) {
        uint32_t Af[4];
        {
            uint32_t row = (uint32_t)(wid * 16 + (lblk & 1) * 8 + lrow);
            uint32_t c16 = (uint32_t)(ks * 2 + (lblk >> 1));
            ldm_x4(Af, aq + swz(row, c16));
        }
        uint32_t Bf[8][2];
        #pragma unroll
        for (int np = 0; np < 4; np++) {
            uint32_t row = (uint32_t)(np * 16 + (lblk >> 1) * 8 + lrow);
            uint32_t c16 = (uint32_t)(ks * 2 + (lblk & 1));
            uint32_t r[4];
            ldm_x4(r, ak + swz(row, c16));
            Bf[np*2][0] = r[0]; Bf[np*2][1] = r[1];
            Bf[np*2+1][0] = r[2]; Bf[np*2+1][1] = r[3];
        }
        #pragma unroll
        for (int nt = 0; nt < 8; nt++) mma16816h(acc[nt], Af, Bf[nt]);
    }

    // ---- softmax in registers ----------------------------------------------
    float mx0 = -1e30f, mx1 = -1e30f;
    #pragma unroll
    for (int nt = 0; nt < 8; nt++) {
        mx0 = fmaxf(mx0, fmaxf(acc[nt][0], acc[nt][1]));
        mx1 = fmaxf(mx1, fmaxf(acc[nt][2], acc[nt][3]));
    }
    #pragma unroll
    for (int d = 1; d <= 2; d <<= 1) {
        mx0 = fmaxf(mx0, __shfl_xor_sync(0xffffffffu, mx0, d));
        mx1 = fmaxf(mx1, __shfl_xor_sync(0xffffffffu, mx1, d));
    }
    float s0 = 0.f, s1 = 0.f;
    #pragma unroll
    for (int nt = 0; nt < 8; nt++) {
        acc[nt][0] = __expf(acc[nt][0] - mx0);
        acc[nt][1] = __expf(acc[nt][1] - mx0);
        acc[nt][2] = __expf(acc[nt][2] - mx1);
        acc[nt][3] = __expf(acc[nt][3] - mx1);
        s0 += acc[nt][0] + acc[nt][1];
        s1 += acc[nt][2] + acc[nt][3];
    }
    #pragma unroll
    for (int d = 1; d <= 2; d <<= 1) {
        s0 += __shfl_xor_sync(0xffffffffu, s0, d);
        s1 += __shfl_xor_sync(0xffffffffu, s1, d);
    }
    const float inv0 = 1.f / s0, inv1 = 1.f / s1;

    // ---- O = P V : P hi/lo 2-pass (in-register), V single fp16 --------------
    float o[4][4] = {};
    #pragma unroll
    for (int j = 0; j < 4; j++) {
        uint32_t aPh[4], aPl[4];
        split2_pack_h(acc[2*j][0],   acc[2*j][1],   aPh[0], aPl[0]);
        split2_pack_h(acc[2*j][2],   acc[2*j][3],   aPh[1], aPl[1]);
        split2_pack_h(acc[2*j+1][0], acc[2*j+1][1], aPh[2], aPl[2]);
        split2_pack_h(acc[2*j+1][2], acc[2*j+1][3], aPh[3], aPl[3]);

        uint32_t Bv[4][2];
        #pragma unroll
        for (int a = 0; a < 2; a++) {
            uint32_t row = (uint32_t)(16 * j + lrow + (lblk & 1) * 8);
            uint32_t c16 = (uint32_t)(2 * a + (lblk >> 1));
            uint32_t r[4];
            ldm_x4_trans(r, av + swz(row, c16));
            Bv[2*a][0] = r[0]; Bv[2*a][1] = r[1];
            Bv[2*a+1][0] = r[2]; Bv[2*a+1][1] = r[3];
        }
        #pragma unroll
        for (int nt = 0; nt < 4; nt++) mma16816h(o[nt], aPh, Bv[nt]);
        #pragma unroll
        for (int nt = 0; nt < 4; nt++) mma16816h(o[nt], aPl, Bv[nt]);
    }

    // ---- epilogue: normalize, fp16, stage in smem (reuse sq), store ---------
    __syncthreads();
    {
        int r0 = 16 * wid + (lane >> 2);
        int cb = (lane & 3) * 2;
        #pragma unroll
        for (int nt = 0; nt < 4; nt++) {
            int d = nt * 8 + cb;
            *reinterpret_cast<uint32_t*>(&sq[r0 * 32 + d]) =
                pack_half2(o[nt][0] * inv0, o[nt][1] * inv0);
            *reinterpret_cast<uint32_t*>(&sq[(r0 + 8) * 32 + d]) =
                pack_half2(o[nt][2] * inv1, o[nt][3] * inv1);
        }
    }
    __syncthreads();
    {
        int tok  = tid >> 1;
        int half = tid & 1;
        int wsh = tok >> 3, wsw = tok & 7;
        int pixo = (hh * 8 + wsh) * 64 + ww * 8 + wsw;
        size_t off = ((size_t)b * HW + pixo) * CCH + head * DHEAD + half * 16;
        // 16 halves (=2 uint4) per thread; 2 threads cover the full 32-ch head
        const uint4* s = reinterpret_cast<const uint4*>(&sq[tok * 32 + half * 16]);
        uint4* d = reinterpret_cast<uint4*>(g_o + off);
        d[0] = s[0];
        d[1] = s[1];
    }
}

// ---------------------------------------------------------------------------
extern "C" void kernel_launch(void* const* d_in, const int* in_sizes, int n_in,
                              void* d_out, int out_size)
{
    const float* x      = (const float*)d_in[0];
    const float* w_qkv  = (const float*)d_in[1];
    const float* b_qkv  = (const float*)d_in[2];
    const float* w_proj = (const float*)d_in[3];
    const float* b_proj = (const float*)d_in[4];
    float* out = (float*)d_out;
    (void)in_sizes; (void)n_in; (void)out_size;

    cudaFuncSetAttribute(gemm_mma_kernel<0>,
                         cudaFuncAttributeMaxDynamicSharedMemorySize, GEMM_SMEM);
    cudaFuncSetAttribute(gemm_mma_kernel<1>,
                         cudaFuncAttributeMaxDynamicSharedMemorySize, GEMM_SMEM);

    weight_half_kernel<<<(QKV_C * CCH + 255) / 256, 256>>>(w_qkv, w_proj);

    dim3 gT(HW / 32, CCH / 32, BATCH);
    transpose_half_kernel<<<gT, 256>>>(x);

    dim3 g1(QKV_C / 128, HW / 128, BATCH);   // n fastest -> A-tile L2 reuse
    gemm_mma_kernel<0><<<g1, 256, GEMM_SMEM>>>(b_qkv, nullptr);

    dim3 gA(64, NHEADS, BATCH);
    attn_mma_kernel<<<gA, 128>>>();

    dim3 g2(CCH / 128, HW / 128, BATCH);
    gemm_mma_kernel<1><<<g2, 256, GEMM_SMEM>>>(b_proj, out);
}

// round 8
// speedup vs baseline: 7.3242x; 1.1325x over previous
#include <cuda_runtime.h>
#include <cuda_fp16.h>
#include <cstdint>

// Problem constants
#define BATCH  16
#define CCH    384
#define HW     4096
#define NHEADS 12
#define DHEAD  32
#define QKV_C  1152

#define BK     64
#define NCHUNK (CCH / BK)   // 6

// ---------------------------------------------------------------------------
// Device-global scratch (no cudaMalloc allowed)
// ---------------------------------------------------------------------------
__device__ __align__(256) __half g_qkv[(size_t)BATCH * HW * QKV_C]; // fp16, q pre-scaled
__device__ __align__(256) __half g_xt[(size_t)BATCH * HW * CCH];    // x^T fp16 [b][pix][c]
__device__ __align__(256) __half g_o [(size_t)BATCH * HW * CCH];    // attn out fp16
__device__ __align__(256) __half g_wq_h[QKV_C * CCH];
__device__ __align__(256) __half g_wp_h[CCH * CCH];

// ---------------------------------------------------------------------------
// Helpers
// ---------------------------------------------------------------------------
__device__ __forceinline__ uint32_t smem_u32(const void* p) {
    uint32_t a;
    asm("{ .reg .u64 t; cvta.to.shared.u64 t, %1; cvt.u32.u64 %0, t; }"
        : "=r"(a) : "l"(p));
    return a;
}

__device__ __forceinline__ uint32_t pack_half2(float a, float b) {
    __half ha = __float2half_rn(a), hb = __float2half_rn(b);
    uint16_t ua = *reinterpret_cast<uint16_t*>(&ha);
    uint16_t ub = *reinterpret_cast<uint16_t*>(&hb);
    return (uint32_t)ua | ((uint32_t)ub << 16);
}

// fp16 hi/lo split of 2 floats packed into 2 u32
__device__ __forceinline__ void split2_pack_h(float a, float b, uint32_t& hi, uint32_t& lo) {
    __half ha = __float2half_rn(a), hb = __float2half_rn(b);
    float ra = a - __half2float(ha), rb = b - __half2float(hb);
    __half la = __float2half_rn(ra), lb = __float2half_rn(rb);
    uint16_t uha = *reinterpret_cast<uint16_t*>(&ha);
    uint16_t uhb = *reinterpret_cast<uint16_t*>(&hb);
    uint16_t ula = *reinterpret_cast<uint16_t*>(&la);
    uint16_t ulb = *reinterpret_cast<uint16_t*>(&lb);
    hi = (uint32_t)uha | ((uint32_t)uhb << 16);
    lo = (uint32_t)ula | ((uint32_t)ulb << 16);
}

// 32-col tile swizzle (attn): rows of 32 halves (64B), 4x16B chunks
__device__ __forceinline__ uint32_t swz(uint32_t row, uint32_t c16) {
    return row * 64u + ((c16 ^ ((row >> 1) & 3u)) * 16u);
}

// 64-col tile swizzle (gemm): rows of 64 halves (128B), 8x16B chunks
__device__ __forceinline__ uint32_t swz128(uint32_t row, uint32_t c16) {
    return row * 128u + ((c16 ^ (row & 7u)) * 16u);
}

__device__ __forceinline__ void ldm_x4(uint32_t* r, uint32_t addr) {
    asm volatile("ldmatrix.sync.aligned.m8n8.x4.shared.b16 {%0,%1,%2,%3}, [%4];"
                 : "=r"(r[0]), "=r"(r[1]), "=r"(r[2]), "=r"(r[3]) : "r"(addr));
}

__device__ __forceinline__ void ldm_x4_trans(uint32_t* r, uint32_t addr) {
    asm volatile("ldmatrix.sync.aligned.m8n8.x4.trans.shared.b16 {%0,%1,%2,%3}, [%4];"
                 : "=r"(r[0]), "=r"(r[1]), "=r"(r[2]), "=r"(r[3]) : "r"(addr));
}

__device__ __forceinline__ void mma16816h(float* c, const uint32_t* a, const uint32_t* b) {
    asm volatile(
        "mma.sync.aligned.m16n8k16.row.col.f32.f16.f16.f32 "
        "{%0,%1,%2,%3}, {%4,%5,%6,%7}, {%8,%9}, {%0,%1,%2,%3};"
        : "+f"(c[0]), "+f"(c[1]), "+f"(c[2]), "+f"(c[3])
        : "r"(a[0]), "r"(a[1]), "r"(a[2]), "r"(a[3]), "r"(b[0]), "r"(b[1]));
}

#define CP_ASYNC16(dst, src) \
    asm volatile("cp.async.cg.shared.global [%0], [%1], 16;" :: "r"(dst), "l"(src))
#define CP_COMMIT() asm volatile("cp.async.commit_group;")
#define CP_WAIT0()  asm volatile("cp.async.wait_group 0;")
#define CP_WAIT1()  asm volatile("cp.async.wait_group 1;")

// load one 128x64 fp16 tile (row stride CCH) into swizzled smem via cp.async
// 1024 chunks of 16B; 256 threads x 4
__device__ __forceinline__ void load_tile64_async(const __half* __restrict__ src,
                                                  int row0, int k0, uint32_t dst, int tid) {
    #pragma unroll
    for (int j = 0; j < 4; j++) {
        int c   = tid + j * 256;
        int row = c >> 3, c16 = c & 7;
        const __half* g = src + (size_t)(row0 + row) * CCH + k0 + c16 * 8;
        CP_ASYNC16(dst + swz128((uint32_t)row, (uint32_t)c16), g);
    }
}

// ---------------------------------------------------------------------------
// Kernel 1: transpose x [b][c][pix] -> fp16 [b][pix][c]
// ---------------------------------------------------------------------------
__global__ __launch_bounds__(256) void transpose_half_kernel(const float* __restrict__ x)
{
    __shared__ float t[32][33];
    const int b  = blockIdx.z;
    const int p0 = blockIdx.x * 32;
    const int c0 = blockIdx.y * 32;
    const int tx = threadIdx.x & 31;
    const int ty = threadIdx.x >> 5;

    const float* xb = x + (size_t)b * CCH * HW;
    #pragma unroll
    for (int i = 0; i < 4; i++)
        t[ty + i * 8][tx] = xb[(size_t)(c0 + ty + i * 8) * HW + p0 + tx];
    __syncthreads();

    #pragma unroll
    for (int i = 0; i < 4; i++) {
        int p = p0 + ty + i * 8;
        int c = c0 + tx;
        g_xt[((size_t)b * HW + p) * CCH + c] = __float2half_rn(t[tx][ty + i * 8]);
    }
}

// ---------------------------------------------------------------------------
// Kernel 2: weights -> fp16 (single rounding)
// ---------------------------------------------------------------------------
__global__ void weight_half_kernel(const float* __restrict__ wq,
                                   const float* __restrict__ wp)
{
    int i = blockIdx.x * blockDim.x + threadIdx.x;
    if (i < QKV_C * CCH) g_wq_h[i] = __float2half_rn(wq[i]);
    if (i < CCH * CCH)   g_wp_h[i] = __float2half_rn(wp[i]);
}

// ---------------------------------------------------------------------------
// Tensor-core GEMM (single-pass fp16 mma, fp32 accumulate)
// D[pix(128)][och(128)] = A[pix][cch] . B[och][cch]^T
// BK=64, 3-stage cp.async pipeline; stage = A(16K) + B(16K) = 32KB.
// G==0: A = g_xt, B = w_qkv -> g_qkv fp16 [b][pix][1152], q cols pre-scaled
// G==1: A = g_o,  B = w_proj -> out  fp32 [b][och][4096]
// ---------------------------------------------------------------------------
#define STAGE_BYTES 32768
#define GEMM_SMEM   98304

template<int G>
__global__ __launch_bounds__(256, 2) void gemm_mma_kernel(const float* __restrict__ bias,
                                                          float* __restrict__ out_base)
{
    extern __shared__ __align__(128) char smem[];
    const uint32_t sbase = smem_u32(smem);
    const int tid = threadIdx.x, wid = tid >> 5, lane = tid & 31;
    const int warp_m = wid & 3;
    const int warp_n = wid >> 2;

    const int b  = blockIdx.z;
    const int n0 = blockIdx.x * 128;   // och tile (x fastest -> A reuse in L2)
    const int m0 = blockIdx.y * 128;   // pixel tile

    const __half* A  = (G == 0 ? g_xt : g_o) + (size_t)b * HW * CCH;
    const __half* Bw = (G == 0 ? g_wq_h : g_wp_h);

    float acc[2][8][4] = {};

    #pragma unroll
    for (int i = 0; i < 2; i++) {
        const uint32_t sb = sbase + i * STAGE_BYTES;
        load_tile64_async(A,  m0, i * BK, sb + 0,     tid);
        load_tile64_async(Bw, n0, i * BK, sb + 16384, tid);
        CP_COMMIT();
    }
    CP_WAIT1();
    __syncthreads();

    const int lrow = lane & 7;
    const int lblk = lane >> 3;

    #pragma unroll 1
    for (int i = 0; i < NCHUNK; i++) {
        if (i + 2 < NCHUNK) {
            const uint32_t nb = sbase + ((i + 2) % 3) * STAGE_BYTES;
            const int k0 = (i + 2) * BK;
            load_tile64_async(A,  m0, k0, nb + 0,     tid);
            load_tile64_async(Bw, n0, k0, nb + 16384, tid);
            CP_COMMIT();
        }

        const uint32_t sA = sbase + (i % 3) * STAGE_BYTES;
        const uint32_t sB = sA + 16384;

        #pragma unroll
        for (int ks = 0; ks < 4; ks++) {
            uint32_t Af[2][4];
            #pragma unroll
            for (int mt = 0; mt < 2; mt++) {
                uint32_t row = (uint32_t)(warp_m * 32 + mt * 16 + (lblk & 1) * 8 + lrow);
                uint32_t c16 = (uint32_t)(ks * 2 + (lblk >> 1));
                ldm_x4(Af[mt], sA + swz128(row, c16));
            }
            uint32_t Bf[8][2];
            #pragma unroll
            for (int np = 0; np < 4; np++) {
                uint32_t row = (uint32_t)(warp_n * 64 + np * 16 + (lblk >> 1) * 8 + lrow);
                uint32_t c16 = (uint32_t)(ks * 2 + (lblk & 1));
                uint32_t r[4];
                ldm_x4(r, sB + swz128(row, c16));
                Bf[np*2][0] = r[0]; Bf[np*2][1] = r[1];
                Bf[np*2+1][0] = r[2]; Bf[np*2+1][1] = r[3];
            }
            #pragma unroll
            for (int mt = 0; mt < 2; mt++)
                #pragma unroll
                for (int nt = 0; nt < 8; nt++)
                    mma16816h(acc[mt][nt], Af[mt], Bf[nt]);
        }

        if (i + 2 < NCHUNK)      CP_WAIT1();
        else if (i + 1 < NCHUNK) CP_WAIT0();
        __syncthreads();
    }

    // ------------------- epilogue -------------------
    if (G == 0) {
        // fp16 out [b][pix][1152]; bias add; q columns (och<384) scaled.
        constexpr int PADH = 136;   // halves per staged row (272B, 16B-mult)
        const float SCALE = 0.17677669529663687f;
        __half* st = reinterpret_cast<__half*>(smem);   // [128][136]
        {
            #pragma unroll
            for (int mt = 0; mt < 2; mt++)
                #pragma unroll
                for (int nt = 0; nt < 8; nt++) {
                    int ml = warp_m * 32 + mt * 16 + (lane >> 2);
                    int nl = warp_n * 64 + nt * 8 + (lane & 3) * 2;
                    int och = n0 + nl;
                    float s  = (och < CCH) ? SCALE : 1.0f;
                    float b0 = bias[och], b1 = bias[och + 1];
                    *reinterpret_cast<uint32_t*>(&st[ml * PADH + nl]) =
                        pack_half2((acc[mt][nt][0] + b0) * s, (acc[mt][nt][1] + b1) * s);
                    *reinterpret_cast<uint32_t*>(&st[(ml + 8) * PADH + nl]) =
                        pack_half2((acc[mt][nt][2] + b0) * s, (acc[mt][nt][3] + b1) * s);
                }
        }
        __syncthreads();
        __half* outb = g_qkv + (size_t)b * HW * QKV_C;
        #pragma unroll
        for (int j = 0; j < 8; j++) {
            int fi  = tid + j * 256;          // 2048 chunks of 8 halves
            int row = fi >> 4;
            int c16 = fi & 15;
            uint4 v = *reinterpret_cast<uint4*>(&st[row * PADH + c16 * 8]);
            *reinterpret_cast<uint4*>(&outb[(size_t)(m0 + row) * QKV_C + n0 + c16 * 8]) = v;
        }
    } else {
        constexpr int PAD = 132;
        float* st = reinterpret_cast<float*>(smem);
        float* outb = out_base + (size_t)b * CCH * HW;
        #pragma unroll 1
        for (int h = 0; h < 2; h++) {
            __syncthreads();
            if (warp_n == h) {
                #pragma unroll
                for (int mt = 0; mt < 2; mt++)
                    #pragma unroll
                    for (int nt = 0; nt < 8; nt++) {
                        int ml = warp_m * 32 + mt * 16 + (lane >> 2);
                        int nl = nt * 8 + (lane & 3) * 2;
                        st[nl * PAD + ml]           = acc[mt][nt][0];
                        st[(nl + 1) * PAD + ml]     = acc[mt][nt][1];
                        st[nl * PAD + ml + 8]       = acc[mt][nt][2];
                        st[(nl + 1) * PAD + ml + 8] = acc[mt][nt][3];
                    }
            }
            __syncthreads();
            #pragma unroll
            for (int j = 0; j < 8; j++) {
                int fi  = tid + j * 256;
                int row = fi >> 5;
                int c4  = (fi & 31) * 4;
                int och = n0 + h * 64 + row;
                float4 v = *reinterpret_cast<float4*>(&st[row * PAD + c4]);
                float bi = bias[och];
                v.x += bi; v.y += bi; v.z += bi; v.w += bi;
                *reinterpret_cast<float4*>(&outb[(size_t)och * HW + m0 + c4]) = v;
            }
        }
    }
}

// ---------------------------------------------------------------------------
// Attention: 1 block = (b, head, window), 4 warps. All-fp16 operands.
// q pre-scaled by producer. S single-pass; P·V: P hi/lo 2-pass, V single.
// Strided windows (faithful to reference).
// ---------------------------------------------------------------------------
__global__ __launch_bounds__(128) void attn_mma_kernel()
{
    __shared__ __align__(128) __half sq[64 * 32];
    __shared__ __align__(128) __half sk[64 * 32];
    __shared__ __align__(128) __half sv[64 * 32];

    const int wi   = blockIdx.x;
    const int head = blockIdx.y;
    const int b    = blockIdx.z;
    const int hh   = wi >> 3;
    const int ww   = wi & 7;
    const int tid  = threadIdx.x;
    const int wid  = tid >> 5;
    const int lane = tid & 31;

    const uint32_t aq = smem_u32(sq), ak = smem_u32(sk), av = smem_u32(sv);

    const __half* base = g_qkv + (size_t)b * HW * QKV_C + (size_t)head * DHEAD;

    // ---- cp.async q,k,v straight into swizzled smem -------------------------
    #pragma unroll
    for (int it = 0; it < 6; it++) {
        int e   = tid + it * 128;
        int ten = e >> 8;              // 0=q 1=k 2=v
        int rem = e & 255;
        int tok = rem >> 2;
        int c16 = rem & 3;
        int wsh = tok >> 3, wsw = tok & 7;
        int pix = (wsh * 8 + hh) * 64 + wsw * 8 + ww;
        const __half* g = base + (size_t)pix * QKV_C + ten * CCH + c16 * 8;
        uint32_t dst = (ten == 0 ? aq : ten == 1 ? ak : av) + swz((uint32_t)tok, (uint32_t)c16);
        CP_ASYNC16(dst, g);
    }
    CP_COMMIT();
    CP_WAIT0();
    __syncthreads();

    const int lrow = lane & 7;
    const int lblk = lane >> 3;

    // ---- S = Q K^T (q pre-scaled), single-pass fp16 -------------------------
    float acc[8][4] = {};
    #pragma unroll
    for (int ks = 0; ks < 2; ks++) {
        uint32_t Af[4];
        {
            uint32_t row = (uint32_t)(wid * 16 + (lblk & 1) * 8 + lrow);
            uint32_t c16 = (uint32_t)(ks * 2 + (lblk >> 1));
            ldm_x4(Af, aq + swz(row, c16));
        }
        uint32_t Bf[8][2];
        #pragma unroll
        for (int np = 0; np < 4; np++) {
            uint32_t row = (uint32_t)(np * 16 + (lblk >> 1) * 8 + lrow);
            uint32_t c16 = (uint32_t)(ks * 2 + (lblk & 1));
            uint32_t r[4];
            ldm_x4(r, ak + swz(row, c16));
            Bf[np*2][0] = r[0]; Bf[np*2][1] = r[1];
            Bf[np*2+1][0] = r[2]; Bf[np*2+1][1] = r[3];
        }
        #pragma unroll
        for (int nt = 0; nt < 8; nt++) mma16816h(acc[nt], Af, Bf[nt]);
    }

    // ---- softmax in registers ----------------------------------------------
    float mx0 = -1e30f, mx1 = -1e30f;
    #pragma unroll
    for (int nt = 0; nt < 8; nt++) {
        mx0 = fmaxf(mx0, fmaxf(acc[nt][0], acc[nt][1]));
        mx1 = fmaxf(mx1, fmaxf(acc[nt][2], acc[nt][3]));
    }
    #pragma unroll
    for (int d = 1; d <= 2; d <<= 1) {
        mx0 = fmaxf(mx0, __shfl_xor_sync(0xffffffffu, mx0, d));
        mx1 = fmaxf(mx1, __shfl_xor_sync(0xffffffffu, mx1, d));
    }
    float s0 = 0.f, s1 = 0.f;
    #pragma unroll
    for (int nt = 0; nt < 8; nt++) {
        acc[nt][0] = __expf(acc[nt][0] - mx0);
        acc[nt][1] = __expf(acc[nt][1] - mx0);
        acc[nt][2] = __expf(acc[nt][2] - mx1);
        acc[nt][3] = __expf(acc[nt][3] - mx1);
        s0 += acc[nt][0] + acc[nt][1];
        s1 += acc[nt][2] + acc[nt][3];
    }
    #pragma unroll
    for (int d = 1; d <= 2; d <<= 1) {
        s0 += __shfl_xor_sync(0xffffffffu, s0, d);
        s1 += __shfl_xor_sync(0xffffffffu, s1, d);
    }
    const float inv0 = 1.f / s0, inv1 = 1.f / s1;

    // ---- O = P V : P hi/lo 2-pass (in-register), V single fp16 --------------
    float o[4][4] = {};
    #pragma unroll
    for (int j = 0; j < 4; j++) {
        uint32_t aPh[4], aPl[4];
        split2_pack_h(acc[2*j][0],   acc[2*j][1],   aPh[0], aPl[0]);
        split2_pack_h(acc[2*j][2],   acc[2*j][3],   aPh[1], aPl[1]);
        split2_pack_h(acc[2*j+1][0], acc[2*j+1][1], aPh[2], aPl[2]);
        split2_pack_h(acc[2*j+1][2], acc[2*j+1][3], aPh[3], aPl[3]);

        uint32_t Bv[4][2];
        #pragma unroll
        for (int a = 0; a < 2; a++) {
            uint32_t row = (uint32_t)(16 * j + lrow + (lblk & 1) * 8);
            uint32_t c16 = (uint32_t)(2 * a + (lblk >> 1));
            uint32_t r[4];
            ldm_x4_trans(r, av + swz(row, c16));
            Bv[2*a][0] = r[0]; Bv[2*a][1] = r[1];
            Bv[2*a+1][0] = r[2]; Bv[2*a+1][1] = r[3];
        }
        #pragma unroll
        for (int nt = 0; nt < 4; nt++) mma16816h(o[nt], aPh, Bv[nt]);
        #pragma unroll
        for (int nt = 0; nt < 4; nt++) mma16816h(o[nt], aPl, Bv[nt]);
    }

    // ---- epilogue: normalize, fp16, stage in smem (reuse sq), store ---------
    __syncthreads();
    {
        int r0 = 16 * wid + (lane >> 2);
        int cb = (lane & 3) * 2;
        #pragma unroll
        for (int nt = 0; nt < 4; nt++) {
            int d = nt * 8 + cb;
            *reinterpret_cast<uint32_t*>(&sq[r0 * 32 + d]) =
                pack_half2(o[nt][0] * inv0, o[nt][1] * inv0);
            *reinterpret_cast<uint32_t*>(&sq[(r0 + 8) * 32 + d]) =
                pack_half2(o[nt][2] * inv1, o[nt][3] * inv1);
        }
    }
    __syncthreads();
    {
        int tok  = tid >> 1;
        int half = tid & 1;
        int wsh = tok >> 3, wsw = tok & 7;
        int pixo = (hh * 8 + wsh) * 64 + ww * 8 + wsw;
        size_t off = ((size_t)b * HW + pixo) * CCH + head * DHEAD + half * 16;
        // 16 halves (=2 uint4) per thread; 2 threads cover the full 32-ch head
        const uint4* s = reinterpret_cast<const uint4*>(&sq[tok * 32 + half * 16]);
        uint4* d = reinterpret_cast<uint4*>(g_o + off);
        d[0] = s[0];
        d[1] = s[1];
    }
}

// ---------------------------------------------------------------------------
extern "C" void kernel_launch(void* const* d_in, const int* in_sizes, int n_in,
                              void* d_out, int out_size)
{
    const float* x      = (const float*)d_in[0];
    const float* w_qkv  = (const float*)d_in[1];
    const float* b_qkv  = (const float*)d_in[2];
    const float* w_proj = (const float*)d_in[3];
    const float* b_proj = (const float*)d_in[4];
    float* out = (float*)d_out;
    (void)in_sizes; (void)n_in; (void)out_size;

    cudaFuncSetAttribute(gemm_mma_kernel<0>,
                         cudaFuncAttributeMaxDynamicSharedMemorySize, GEMM_SMEM);
    cudaFuncSetAttribute(gemm_mma_kernel<1>,
                         cudaFuncAttributeMaxDynamicSharedMemorySize, GEMM_SMEM);

    weight_half_kernel<<<(QKV_C * CCH + 255) / 256, 256>>>(w_qkv, w_proj);

    dim3 gT(HW / 32, CCH / 32, BATCH);
    transpose_half_kernel<<<gT, 256>>>(x);

    dim3 g1(QKV_C / 128, HW / 128, BATCH);   // n fastest -> A-tile L2 reuse
    gemm_mma_kernel<0><<<g1, 256, GEMM_SMEM>>>(b_qkv, nullptr);

    dim3 gA(64, NHEADS, BATCH);
    attn_mma_kernel<<<gA, 128>>>();

    dim3 g2(CCH / 128, HW / 128, BATCH);
    gemm_mma_kernel<1><<<g2, 256, GEMM_SMEM>>>(b_proj, out);
}

// round 9
// speedup vs baseline: 7.4177x; 1.0128x over previous
#include <cuda_runtime.h>
#include <cuda_fp16.h>
#include <cstdint>

// Problem constants
#define BATCH  16
#define CCH    384
#define HW     4096
#define NHEADS 12
#define DHEAD  32
#define QKV_C  1152

#define BK     64
#define NCHUNK (CCH / BK)   // 6

// ---------------------------------------------------------------------------
// Device-global scratch (no cudaMalloc allowed)
// ---------------------------------------------------------------------------
__device__ __align__(256) __half g_qkv[(size_t)BATCH * HW * QKV_C]; // fp16, q pre-scaled
__device__ __align__(256) __half g_xt[(size_t)BATCH * HW * CCH];    // x^T fp16 [b][pix][c]
__device__ __align__(256) __half g_o [(size_t)BATCH * HW * CCH];    // attn out fp16
__device__ __align__(256) __half g_wq_h[QKV_C * CCH];
__device__ __align__(256) __half g_wp_h[CCH * CCH];

// ---------------------------------------------------------------------------
// Helpers
// ---------------------------------------------------------------------------
__device__ __forceinline__ uint32_t smem_u32(const void* p) {
    uint32_t a;
    asm("{ .reg .u64 t; cvta.to.shared.u64 t, %1; cvt.u32.u64 %0, t; }"
        : "=r"(a) : "l"(p));
    return a;
}

__device__ __forceinline__ uint32_t pack_half2(float a, float b) {
    __half ha = __float2half_rn(a), hb = __float2half_rn(b);
    uint16_t ua = *reinterpret_cast<uint16_t*>(&ha);
    uint16_t ub = *reinterpret_cast<uint16_t*>(&hb);
    return (uint32_t)ua | ((uint32_t)ub << 16);
}

// fp16 hi/lo split of 2 floats packed into 2 u32
__device__ __forceinline__ void split2_pack_h(float a, float b, uint32_t& hi, uint32_t& lo) {
    __half ha = __float2half_rn(a), hb = __float2half_rn(b);
    float ra = a - __half2float(ha), rb = b - __half2float(hb);
    __half la = __float2half_rn(ra), lb = __float2half_rn(rb);
    uint16_t uha = *reinterpret_cast<uint16_t*>(&ha);
    uint16_t uhb = *reinterpret_cast<uint16_t*>(&hb);
    uint16_t ula = *reinterpret_cast<uint16_t*>(&la);
    uint16_t ulb = *reinterpret_cast<uint16_t*>(&lb);
    hi = (uint32_t)uha | ((uint32_t)uhb << 16);
    lo = (uint32_t)ula | ((uint32_t)ulb << 16);
}

// 32-col tile swizzle (attn): rows of 32 halves (64B), 4x16B chunks
__device__ __forceinline__ uint32_t swz(uint32_t row, uint32_t c16) {
    return row * 64u + ((c16 ^ ((row >> 1) & 3u)) * 16u);
}

// 64-col tile swizzle (gemm): rows of 64 halves (128B), 8x16B chunks
__device__ __forceinline__ uint32_t swz128(uint32_t row, uint32_t c16) {
    return row * 128u + ((c16 ^ (row & 7u)) * 16u);
}

__device__ __forceinline__ void ldm_x4(uint32_t* r, uint32_t addr) {
    asm volatile("ldmatrix.sync.aligned.m8n8.x4.shared.b16 {%0,%1,%2,%3}, [%4];"
                 : "=r"(r[0]), "=r"(r[1]), "=r"(r[2]), "=r"(r[3]) : "r"(addr));
}

__device__ __forceinline__ void ldm_x4_trans(uint32_t* r, uint32_t addr) {
    asm volatile("ldmatrix.sync.aligned.m8n8.x4.trans.shared.b16 {%0,%1,%2,%3}, [%4];"
                 : "=r"(r[0]), "=r"(r[1]), "=r"(r[2]), "=r"(r[3]) : "r"(addr));
}

__device__ __forceinline__ void mma16816h(float* c, const uint32_t* a, const uint32_t* b) {
    asm volatile(
        "mma.sync.aligned.m16n8k16.row.col.f32.f16.f16.f32 "
        "{%0,%1,%2,%3}, {%4,%5,%6,%7}, {%8,%9}, {%0,%1,%2,%3};"
        : "+f"(c[0]), "+f"(c[1]), "+f"(c[2]), "+f"(c[3])
        : "r"(a[0]), "r"(a[1]), "r"(a[2]), "r"(a[3]), "r"(b[0]), "r"(b[1]));
}

#define CP_ASYNC16(dst, src) \
    asm volatile("cp.async.cg.shared.global [%0], [%1], 16;" :: "r"(dst), "l"(src))
#define CP_COMMIT() asm volatile("cp.async.commit_group;")
#define CP_WAIT0()  asm volatile("cp.async.wait_group 0;")
#define CP_WAIT1()  asm volatile("cp.async.wait_group 1;")

// load one 128x64 fp16 tile (row stride CCH) into swizzled smem via cp.async
// 1024 chunks of 16B; 128 threads x 8
__device__ __forceinline__ void load_tile64_async(const __half* __restrict__ src,
                                                  int row0, int k0, uint32_t dst, int tid) {
    #pragma unroll
    for (int j = 0; j < 8; j++) {
        int c   = tid + j * 128;
        int row = c >> 3, c16 = c & 7;
        const __half* g = src + (size_t)(row0 + row) * CCH + k0 + c16 * 8;
        CP_ASYNC16(dst + swz128((uint32_t)row, (uint32_t)c16), g);
    }
}

// ---------------------------------------------------------------------------
// Kernel 1: transpose x [b][c][pix] -> fp16 [b][pix][c]
// ---------------------------------------------------------------------------
__global__ __launch_bounds__(256) void transpose_half_kernel(const float* __restrict__ x)
{
    __shared__ float t[32][33];
    const int b  = blockIdx.z;
    const int p0 = blockIdx.x * 32;
    const int c0 = blockIdx.y * 32;
    const int tx = threadIdx.x & 31;
    const int ty = threadIdx.x >> 5;

    const float* xb = x + (size_t)b * CCH * HW;
    #pragma unroll
    for (int i = 0; i < 4; i++)
        t[ty + i * 8][tx] = xb[(size_t)(c0 + ty + i * 8) * HW + p0 + tx];
    __syncthreads();

    #pragma unroll
    for (int i = 0; i < 4; i++) {
        int p = p0 + ty + i * 8;
        int c = c0 + tx;
        g_xt[((size_t)b * HW + p) * CCH + c] = __float2half_rn(t[tx][ty + i * 8]);
    }
}

// ---------------------------------------------------------------------------
// Kernel 2: weights -> fp16 (single rounding)
// ---------------------------------------------------------------------------
__global__ void weight_half_kernel(const float* __restrict__ wq,
                                   const float* __restrict__ wp)
{
    int i = blockIdx.x * blockDim.x + threadIdx.x;
    if (i < QKV_C * CCH) g_wq_h[i] = __float2half_rn(wq[i]);
    if (i < CCH * CCH)   g_wp_h[i] = __float2half_rn(wp[i]);
}

// ---------------------------------------------------------------------------
// Tensor-core GEMM (single-pass fp16 mma, fp32 accumulate)
// D[pix(128)][och(128)] = A[pix][cch] . B[och][cch]^T
// 4 warps, warp tile 64x64 (high smem arithmetic intensity).
// BK=64, 3-stage cp.async pipeline; stage = A(16K) + B(16K) = 32KB.
// G==0: A = g_xt, B = w_qkv -> g_qkv fp16 [b][pix][1152], q cols pre-scaled
// G==1: A = g_o,  B = w_proj -> out  fp32 [b][och][4096]
// ---------------------------------------------------------------------------
#define STAGE_BYTES 32768
#define GEMM_SMEM   98304

template<int G>
__global__ __launch_bounds__(128, 2) void gemm_mma_kernel(const float* __restrict__ bias,
                                                          float* __restrict__ out_base)
{
    extern __shared__ __align__(128) char smem[];
    const uint32_t sbase = smem_u32(smem);
    const int tid = threadIdx.x, wid = tid >> 5, lane = tid & 31;
    const int warp_m = wid & 1;        // 2 warps along m (64 rows each)
    const int warp_n = wid >> 1;       // 2 warps along n (64 cols each)

    const int b  = blockIdx.z;
    const int n0 = blockIdx.x * 128;   // och tile (x fastest -> A reuse in L2)
    const int m0 = blockIdx.y * 128;   // pixel tile

    const __half* A  = (G == 0 ? g_xt : g_o) + (size_t)b * HW * CCH;
    const __half* Bw = (G == 0 ? g_wq_h : g_wp_h);

    float acc[4][8][4] = {};

    #pragma unroll
    for (int i = 0; i < 2; i++) {
        const uint32_t sb = sbase + i * STAGE_BYTES;
        load_tile64_async(A,  m0, i * BK, sb + 0,     tid);
        load_tile64_async(Bw, n0, i * BK, sb + 16384, tid);
        CP_COMMIT();
    }
    CP_WAIT1();
    __syncthreads();

    const int lrow = lane & 7;
    const int lblk = lane >> 3;

    #pragma unroll 1
    for (int i = 0; i < NCHUNK; i++) {
        if (i + 2 < NCHUNK) {
            const uint32_t nb = sbase + ((i + 2) % 3) * STAGE_BYTES;
            const int k0 = (i + 2) * BK;
            load_tile64_async(A,  m0, k0, nb + 0,     tid);
            load_tile64_async(Bw, n0, k0, nb + 16384, tid);
            CP_COMMIT();
        }

        const uint32_t sA = sbase + (i % 3) * STAGE_BYTES;
        const uint32_t sB = sA + 16384;

        #pragma unroll
        for (int ks = 0; ks < 4; ks++) {
            uint32_t Af[4][4];
            #pragma unroll
            for (int mt = 0; mt < 4; mt++) {
                uint32_t row = (uint32_t)(warp_m * 64 + mt * 16 + (lblk & 1) * 8 + lrow);
                uint32_t c16 = (uint32_t)(ks * 2 + (lblk >> 1));
                ldm_x4(Af[mt], sA + swz128(row, c16));
            }
            uint32_t Bf[8][2];
            #pragma unroll
            for (int np = 0; np < 4; np++) {
                uint32_t row = (uint32_t)(warp_n * 64 + np * 16 + (lblk >> 1) * 8 + lrow);
                uint32_t c16 = (uint32_t)(ks * 2 + (lblk & 1));
                uint32_t r[4];
                ldm_x4(r, sB + swz128(row, c16));
                Bf[np*2][0] = r[0]; Bf[np*2][1] = r[1];
                Bf[np*2+1][0] = r[2]; Bf[np*2+1][1] = r[3];
            }
            #pragma unroll
            for (int mt = 0; mt < 4; mt++)
                #pragma unroll
                for (int nt = 0; nt < 8; nt++)
                    mma16816h(acc[mt][nt], Af[mt], Bf[nt]);
        }

        if (i + 2 < NCHUNK)      CP_WAIT1();
        else if (i + 1 < NCHUNK) CP_WAIT0();
        __syncthreads();
    }

    // ------------------- epilogue -------------------
    if (G == 0) {
        // fp16 out [b][pix][1152]; bias add; q columns (och<384) scaled.
        constexpr int PADH = 136;   // halves per staged row (272B, 16B-mult)
        const float SCALE = 0.17677669529663687f;
        __half* st = reinterpret_cast<__half*>(smem);   // [128][136]
        {
            #pragma unroll
            for (int mt = 0; mt < 4; mt++)
                #pragma unroll
                for (int nt = 0; nt < 8; nt++) {
                    int ml = warp_m * 64 + mt * 16 + (lane >> 2);
                    int nl = warp_n * 64 + nt * 8 + (lane & 3) * 2;
                    int och = n0 + nl;
                    float s  = (och < CCH) ? SCALE : 1.0f;
                    float b0 = bias[och], b1 = bias[och + 1];
                    *reinterpret_cast<uint32_t*>(&st[ml * PADH + nl]) =
                        pack_half2((acc[mt][nt][0] + b0) * s, (acc[mt][nt][1] + b1) * s);
                    *reinterpret_cast<uint32_t*>(&st[(ml + 8) * PADH + nl]) =
                        pack_half2((acc[mt][nt][2] + b0) * s, (acc[mt][nt][3] + b1) * s);
                }
        }
        __syncthreads();
        __half* outb = g_qkv + (size_t)b * HW * QKV_C;
        #pragma unroll
        for (int j = 0; j < 16; j++) {
            int fi  = tid + j * 128;          // 2048 chunks of 8 halves
            int row = fi >> 4;
            int c16 = fi & 15;
            uint4 v = *reinterpret_cast<uint4*>(&st[row * PADH + c16 * 8]);
            *reinterpret_cast<uint4*>(&outb[(size_t)(m0 + row) * QKV_C + n0 + c16 * 8]) = v;
        }
    } else {
        constexpr int PAD = 132;
        float* st = reinterpret_cast<float*>(smem);     // [64][132]
        float* outb = out_base + (size_t)b * CCH * HW;
        #pragma unroll 1
        for (int h = 0; h < 2; h++) {
            __syncthreads();
            if (warp_n == h) {
                #pragma unroll
                for (int mt = 0; mt < 4; mt++)
                    #pragma unroll
                    for (int nt = 0; nt < 8; nt++) {
                        int ml = warp_m * 64 + mt * 16 + (lane >> 2);
                        int nl = nt * 8 + (lane & 3) * 2;
                        st[nl * PAD + ml]           = acc[mt][nt][0];
                        st[(nl + 1) * PAD + ml]     = acc[mt][nt][1];
                        st[nl * PAD + ml + 8]       = acc[mt][nt][2];
                        st[(nl + 1) * PAD + ml + 8] = acc[mt][nt][3];
                    }
            }
            __syncthreads();
            #pragma unroll
            for (int j = 0; j < 16; j++) {
                int fi  = tid + j * 128;
                int row = fi >> 5;
                int c4  = (fi & 31) * 4;
                int och = n0 + h * 64 + row;
                float4 v = *reinterpret_cast<float4*>(&st[row * PAD + c4]);
                float bi = bias[och];
                v.x += bi; v.y += bi; v.z += bi; v.w += bi;
                *reinterpret_cast<float4*>(&outb[(size_t)och * HW + m0 + c4]) = v;
            }
        }
    }
}

// ---------------------------------------------------------------------------
// Attention: 1 block = (b, head, window), 4 warps. All-fp16 operands.
// q pre-scaled by producer. S single-pass; P·V: P hi/lo 2-pass, V single.
// Strided windows (faithful to reference).
// ---------------------------------------------------------------------------
__global__ __launch_bounds__(128) void attn_mma_kernel()
{
    __shared__ __align__(128) __half sq[64 * 32];
    __shared__ __align__(128) __half sk[64 * 32];
    __shared__ __align__(128) __half sv[64 * 32];

    const int wi   = blockIdx.x;
    const int head = blockIdx.y;
    const int b    = blockIdx.z;
    const int hh   = wi >> 3;
    const int ww   = wi & 7;
    const int tid  = threadIdx.x;
    const int wid  = tid >> 5;
    const int lane = tid & 31;

    const uint32_t aq = smem_u32(sq), ak = smem_u32(sk), av = smem_u32(sv);

    const __half* base = g_qkv + (size_t)b * HW * QKV_C + (size_t)head * DHEAD;

    // ---- cp.async q,k,v straight into swizzled smem -------------------------
    #pragma unroll
    for (int it = 0; it < 6; it++) {
        int e   = tid + it * 128;
        int ten = e >> 8;              // 0=q 1=k 2=v
        int rem = e & 255;
        int tok = rem >> 2;
        int c16 = rem & 3;
        int wsh = tok >> 3, wsw = tok & 7;
        int pix = (wsh * 8 + hh) * 64 + wsw * 8 + ww;
        const __half* g = base + (size_t)pix * QKV_C + ten * CCH + c16 * 8;
        uint32_t dst = (ten == 0 ? aq : ten == 1 ? ak : av) + swz((uint32_t)tok, (uint32_t)c16);
        CP_ASYNC16(dst, g);
    }
    CP_COMMIT();
    CP_WAIT0();
    __syncthreads();

    const int lrow = lane & 7;
    const int lblk = lane >> 3;

    // ---- S = Q K^T (q pre-scaled), single-pass fp16 -------------------------
    float acc[8][4] = {};
    #pragma unroll
    for (int ks = 0; ks < 2; ks++) {
        uint32_t Af[4];
        {
            uint32_t row = (uint32_t)(wid * 16 + (lblk & 1) * 8 + lrow);
            uint32_t c16 = (uint32_t)(ks * 2 + (lblk >> 1));
            ldm_x4(Af, aq + swz(row, c16));
        }
        uint32_t Bf[8][2];
        #pragma unroll
        for (int np = 0; np < 4; np++) {
            uint32_t row = (uint32_t)(np * 16 + (lblk >> 1) * 8 + lrow);
            uint32_t c16 = (uint32_t)(ks * 2 + (lblk & 1));
            uint32_t r[4];
            ldm_x4(r, ak + swz(row, c16));
            Bf[np*2][0] = r[0]; Bf[np*2][1] = r[1];
            Bf[np*2+1][0] = r[2]; Bf[np*2+1][1] = r[3];
        }
        #pragma unroll
        for (int nt = 0; nt < 8; nt++) mma16816h(acc[nt], Af, Bf[nt]);
    }

    // ---- softmax in registers ----------------------------------------------
    float mx0 = -1e30f, mx1 = -1e30f;
    #pragma unroll
    for (int nt = 0; nt < 8; nt++) {
        mx0 = fmaxf(mx0, fmaxf(acc[nt][0], acc[nt][1]));
        mx1 = fmaxf(mx1, fmaxf(acc[nt][2], acc[nt][3]));
    }
    #pragma unroll
    for (int d = 1; d <= 2; d <<= 1) {
        mx0 = fmaxf(mx0, __shfl_xor_sync(0xffffffffu, mx0, d));
        mx1 = fmaxf(mx1, __shfl_xor_sync(0xffffffffu, mx1, d));
    }
    float s0 = 0.f, s1 = 0.f;
    #pragma unroll
    for (int nt = 0; nt < 8; nt++) {
        acc[nt][0] = __expf(acc[nt][0] - mx0);
        acc[nt][1] = __expf(acc[nt][1] - mx0);
        acc[nt][2] = __expf(acc[nt][2] - mx1);
        acc[nt][3] = __expf(acc[nt][3] - mx1);
        s0 += acc[nt][0] + acc[nt][1];
        s1 += acc[nt][2] + acc[nt][3];
    }
    #pragma unroll
    for (int d = 1; d <= 2; d <<= 1) {
        s0 += __shfl_xor_sync(0xffffffffu, s0, d);
        s1 += __shfl_xor_sync(0xffffffffu, s1, d);
    }
    const float inv0 = 1.f / s0, inv1 = 1.f / s1;

    // ---- O = P V : P hi/lo 2-pass (in-register), V single fp16 --------------
    float o[4][4] = {};
    #pragma unroll
    for (int j = 0; j < 4; j++) {
        uint32_t aPh[4], aPl[4];
        split2_pack_h(acc[2*j][0],   acc[2*j][1],   aPh[0], aPl[0]);
        split2_pack_h(acc[2*j][2],   acc[2*j][3],   aPh[1], aPl[1]);
        split2_pack_h(acc[2*j+1][0], acc[2*j+1][1], aPh[2], aPl[2]);
        split2_pack_h(acc[2*j+1][2], acc[2*j+1][3], aPh[3], aPl[3]);

        uint32_t Bv[4][2];
        #pragma unroll
        for (int a = 0; a < 2; a++) {
            uint32_t row = (uint32_t)(16 * j + lrow + (lblk & 1) * 8);
            uint32_t c16 = (uint32_t)(2 * a + (lblk >> 1));
            uint32_t r[4];
            ldm_x4_trans(r, av + swz(row, c16));
            Bv[2*a][0] = r[0]; Bv[2*a][1] = r[1];
            Bv[2*a+1][0] = r[2]; Bv[2*a+1][1] = r[3];
        }
        #pragma unroll
        for (int nt = 0; nt < 4; nt++) mma16816h(o[nt], aPh, Bv[nt]);
        #pragma unroll
        for (int nt = 0; nt < 4; nt++) mma16816h(o[nt], aPl, Bv[nt]);
    }

    // ---- epilogue: normalize, fp16, stage in smem (reuse sq), store ---------
    __syncthreads();
    {
        int r0 = 16 * wid + (lane >> 2);
        int cb = (lane & 3) * 2;
        #pragma unroll
        for (int nt = 0; nt < 4; nt++) {
            int d = nt * 8 + cb;
            *reinterpret_cast<uint32_t*>(&sq[r0 * 32 + d]) =
                pack_half2(o[nt][0] * inv0, o[nt][1] * inv0);
            *reinterpret_cast<uint32_t*>(&sq[(r0 + 8) * 32 + d]) =
                pack_half2(o[nt][2] * inv1, o[nt][3] * inv1);
        }
    }
    __syncthreads();
    {
        int tok  = tid >> 1;
        int half = tid & 1;
        int wsh = tok >> 3, wsw = tok & 7;
        int pixo = (hh * 8 + wsh) * 64 + ww * 8 + wsw;
        size_t off = ((size_t)b * HW + pixo) * CCH + head * DHEAD + half * 16;
        const uint4* s = reinterpret_cast<const uint4*>(&sq[tok * 32 + half * 16]);
        uint4* d = reinterpret_cast<uint4*>(g_o + off);
        d[0] = s[0];
        d[1] = s[1];
    }
}

// ---------------------------------------------------------------------------
extern "C" void kernel_launch(void* const* d_in, const int* in_sizes, int n_in,
                              void* d_out, int out_size)
{
    const float* x      = (const float*)d_in[0];
    const float* w_qkv  = (const float*)d_in[1];
    const float* b_qkv  = (const float*)d_in[2];
    const float* w_proj = (const float*)d_in[3];
    const float* b_proj = (const float*)d_in[4];
    float* out = (float*)d_out;
    (void)in_sizes; (void)n_in; (void)out_size;

    cudaFuncSetAttribute(gemm_mma_kernel<0>,
                         cudaFuncAttributeMaxDynamicSharedMemorySize, GEMM_SMEM);
    cudaFuncSetAttribute(gemm_mma_kernel<1>,
                         cudaFuncAttributeMaxDynamicSharedMemorySize, GEMM_SMEM);

    weight_half_kernel<<<(QKV_C * CCH + 255) / 256, 256>>>(w_qkv, w_proj);

    dim3 gT(HW / 32, CCH / 32, BATCH);
    transpose_half_kernel<<<gT, 256>>>(x);

    dim3 g1(QKV_C / 128, HW / 128, BATCH);   // n fastest -> A-tile L2 reuse
    gemm_mma_kernel<0><<<g1, 128, GEMM_SMEM>>>(b_qkv, nullptr);

    dim3 gA(64, NHEADS, BATCH);
    attn_mma_kernel<<<gA, 128>>>();

    dim3 g2(CCH / 128, HW / 128, BATCH);
    gemm_mma_kernel<1><<<g2, 128, GEMM_SMEM>>>(b_proj, out);
}